// round 10
// baseline (speedup 1.0000x reference)
#include <cuda_runtime.h>
#include <cuda_fp16.h>
#include <math.h>
#include <stdint.h>

#define P 64
#define NMAX 4096

// ---------------- persistent device scratch ----------------
__device__ float g_sq[NMAX];
__device__ __half g_D2h[(size_t)NMAX * NMAX];
__device__ unsigned int g_maxbits;
__device__ float g_S1[NMAX];
__device__ float g_mun[NMAX * P];
__device__ float g_bU[NMAX];
__device__ float g_sU2[NMAX];
__device__ float g_S2[NMAX];
__device__ float g_accZ[NMAX * P];
__device__ __half g_xh[NMAX * P], g_xl[NMAX * P];
__device__ __half g_Uh[NMAX * P], g_Ul[NMAX * P];
__device__ unsigned int g_cntA[NMAX / 128];
__device__ unsigned int g_cntB[NMAX / 128];

// ---------------- helpers ----------------
__device__ __forceinline__ uint32_t su32(const void* p) {
    uint32_t a;
    asm("{ .reg .u64 t; cvta.to.shared.u64 t, %1; cvt.u32.u64 %0, t; }" : "=r"(a) : "l"(p));
    return a;
}
#define SWZ(b) ((uint32_t)(b) ^ ((((uint32_t)(b)) >> 3) & 0x70))

__device__ __forceinline__ uint32_t frag_addr(uint32_t base, int lane, int row0, int col0) {
    int r = row0 + (lane & 7) + ((lane >> 3) & 1) * 8;
    int cb = (col0 + (lane >> 4) * 8) * 2;
    return base + SWZ(r * 128 + cb);
}
__device__ __forceinline__ void ldm_x4(uint32_t* r, uint32_t a) {
    asm volatile("ldmatrix.sync.aligned.m8n8.x4.shared.b16 {%0,%1,%2,%3}, [%4];"
                 : "=r"(r[0]), "=r"(r[1]), "=r"(r[2]), "=r"(r[3]) : "r"(a));
}
__device__ __forceinline__ void ldm_x4t(uint32_t* r, uint32_t a) {
    asm volatile("ldmatrix.sync.aligned.m8n8.x4.trans.shared.b16 {%0,%1,%2,%3}, [%4];"
                 : "=r"(r[0]), "=r"(r[1]), "=r"(r[2]), "=r"(r[3]) : "r"(a));
}
__device__ __forceinline__ void mma16816(float* c, const uint32_t* a, const uint32_t* b) {
    asm volatile(
        "mma.sync.aligned.m16n8k16.row.col.f32.f16.f16.f32 "
        "{%0,%1,%2,%3}, {%4,%5,%6,%7}, {%8,%9}, {%0,%1,%2,%3};"
        : "+f"(c[0]), "+f"(c[1]), "+f"(c[2]), "+f"(c[3])
        : "r"(a[0]), "r"(a[1]), "r"(a[2]), "r"(a[3]), "r"(b[0]), "r"(b[1]));
}
__device__ __forceinline__ uint32_t packh2(float a, float b) {
    __half2 h = __floats2half2_rn(a, b);
    return *(uint32_t*)&h;
}
__device__ __forceinline__ float asqrt(float x) { float r; asm("sqrt.approx.f32 %0,%1;" : "=f"(r) : "f"(x)); return r; }
__device__ __forceinline__ float w1f(float d2, float R2i) {
    float s = fmaxf(fmaf(-d2, R2i, 1.0f), 0.0f);
    return s * s * s;
}
__device__ __forceinline__ float w2f(float d, float a) {
    float t = __saturatef(fmaf(d, a, -1.0f));
    float s = fmaf(-t, t, 1.0f);
    return s * s * s;
}

// ---------------- K: prep — sq norms + fp16 split + zero-init ----------------
__global__ void k_prep(const float* __restrict__ x, int n) {
    int gt = blockIdx.x * blockDim.x + threadIdx.x;
    int w = gt >> 5;
    int lane = threadIdx.x & 31;
    *(float2*)&g_mun[(size_t)gt * 2] = make_float2(0.f, 0.f);
    if (gt < n) g_S1[gt] = 0.f;
    if (gt < n / 128) { g_cntA[gt] = 0u; g_cntB[gt] = 0u; }
    if (gt == 0) g_maxbits = 0u;
    if (w >= n) return;
    float v0 = x[(size_t)w * P + lane], v1 = x[(size_t)w * P + 32 + lane];
    __half h0 = __float2half_rn(v0), h1 = __float2half_rn(v1);
    g_xh[(size_t)w * P + lane] = h0;
    g_xh[(size_t)w * P + 32 + lane] = h1;
    g_xl[(size_t)w * P + lane] = __float2half_rn(v0 - __half2float(h0));
    g_xl[(size_t)w * P + 32 + lane] = __float2half_rn(v1 - __half2float(h1));
    float s = v0 * v0 + v1 * v1;
    #pragma unroll
    for (int o = 16; o; o >>= 1) s += __shfl_xor_sync(0xffffffffu, s, o);
    if (lane == 0) g_sq[w] = s;
}

// ---------------- K: gram (upper-triangle) -> D2h, mirror store ----------------
__global__ void __launch_bounds__(256) k_gram(int n) {
    extern __shared__ char smc[];
    __shared__ float wmax[8];
    uint32_t sb = su32(smc);
    const int t = threadIdx.x, w = t >> 5, lane = t & 31;
    const int nb = n >> 7;
    int k = blockIdx.x, a = 0;
    while (k >= nb - a) { k -= nb - a; a++; }
    const int ti = a, tj = a + k;
    const int i0 = ti * 128, j0 = tj * 128;
    float* sqi = (float*)(smc + 49152);
    float* sqj = (float*)(smc + 49664);
    char* stage = smc + 16384;

    for (int q = t; q < 1024; q += 256) {
        int row = q >> 3, cb = (q & 7) * 16;
        uint32_t off = SWZ(row * 128 + cb);
        *(uint4*)(smc + off)         = *(const uint4*)&g_xh[(size_t)(i0 + row) * P + cb / 2];
        *(uint4*)(smc + 16384 + off) = *(const uint4*)&g_xh[(size_t)(j0 + row) * P + cb / 2];
        *(uint4*)(smc + 32768 + off) = *(const uint4*)&g_xl[(size_t)(j0 + row) * P + cb / 2];
    }
    if (t < 128) sqi[t] = g_sq[i0 + t];
    else sqj[t - 128] = g_sq[j0 + t - 128];
    __syncthreads();

    const int m0 = (w & 3) * 32, n0w = (w >> 2) * 64;
    float C[2][8][4];
    #pragma unroll
    for (int a2 = 0; a2 < 2; a2++)
        #pragma unroll
        for (int b = 0; b < 8; b++)
            #pragma unroll
            for (int e = 0; e < 4; e++) C[a2][b][e] = 0.f;

    #pragma unroll
    for (int ks = 0; ks < 4; ks++) {
        int k0 = ks * 16;
        uint32_t Ah[2][4];
        #pragma unroll
        for (int mi = 0; mi < 2; mi++)
            ldm_x4(Ah[mi], frag_addr(sb, lane, m0 + mi * 16, k0));
        #pragma unroll
        for (int gq = 0; gq < 4; gq++) {
            uint32_t Bh[4], Bl[4];
            ldm_x4(Bh, frag_addr(sb + 16384, lane, n0w + gq * 16, k0));
            ldm_x4(Bl, frag_addr(sb + 32768, lane, n0w + gq * 16, k0));
            #pragma unroll
            for (int h = 0; h < 2; h++) {
                int ni = gq * 2 + h;
                uint32_t bh[2] = {Bh[h], Bh[h + 2]};
                uint32_t bl[2] = {Bl[h], Bl[h + 2]};
                #pragma unroll
                for (int mi = 0; mi < 2; mi++) {
                    mma16816(C[mi][ni], Ah[mi], bh);
                    mma16816(C[mi][ni], Ah[mi], bl);
                }
            }
        }
    }
    __syncthreads();

    const int g = lane >> 2, tg = lane & 3;
    float lmax = 0.f;
    #pragma unroll
    for (int mi = 0; mi < 2; mi++)
        #pragma unroll
        for (int e2 = 0; e2 < 2; e2++) {
            int i = m0 + mi * 16 + g + e2 * 8;
            float si = sqi[i];
            #pragma unroll
            for (int ni = 0; ni < 8; ni++) {
                int j = n0w + ni * 8 + tg * 2;
                float d0 = fmaxf(si + sqj[j]     - 2.f * C[mi][ni][e2 * 2],     0.f);
                float d1 = fmaxf(si + sqj[j + 1] - 2.f * C[mi][ni][e2 * 2 + 1], 0.f);
                lmax = fmaxf(lmax, fmaxf(d0, d1));
                *(uint32_t*)(stage + i * 256 + ((j * 2) ^ ((i & 7) << 4))) = packh2(d0, d1);
            }
        }
    #pragma unroll
    for (int o = 16; o; o >>= 1) lmax = fmaxf(lmax, __shfl_xor_sync(0xffffffffu, lmax, o));
    if (lane == 0) wmax[w] = lmax;
    __syncthreads();
    if (t == 0) {
        float m = wmax[0];
        #pragma unroll
        for (int q = 1; q < 8; q++) m = fmaxf(m, wmax[q]);
        atomicMax(&g_maxbits, __float_as_uint(m));
    }
    #pragma unroll
    for (int m = 0; m < 8; m++) {
        int fi = t + 256 * m;
        int row = fi >> 4, c16 = fi & 15;
        uint4 v = *(uint4*)(stage + row * 256 + ((c16 * 16) ^ ((row & 7) << 4)));
        *(uint4*)&g_D2h[(size_t)(i0 + row) * n + j0 + c16 * 8] = v;
    }

    if (ti == tj) return;

    __syncthreads();
    #pragma unroll
    for (int mi = 0; mi < 2; mi++)
        #pragma unroll
        for (int e2 = 0; e2 < 2; e2++) {
            int i = m0 + mi * 16 + g + e2 * 8;
            float si = sqi[i];
            #pragma unroll
            for (int ni = 0; ni < 8; ni++) {
                int j = n0w + ni * 8 + tg * 2;
                float d0 = fmaxf(si + sqj[j]     - 2.f * C[mi][ni][e2 * 2],     0.f);
                float d1 = fmaxf(si + sqj[j + 1] - 2.f * C[mi][ni][e2 * 2 + 1], 0.f);
                __half h0 = __float2half_rn(d0), h1 = __float2half_rn(d1);
                *(__half*)(stage + j * 256 + ((i * 2) ^ ((j & 7) << 4)))             = h0;
                *(__half*)(stage + (j + 1) * 256 + ((i * 2) ^ (((j + 1) & 7) << 4))) = h1;
            }
        }
    __syncthreads();
    #pragma unroll
    for (int m = 0; m < 8; m++) {
        int fi = t + 256 * m;
        int row = fi >> 4, c16 = fi & 15;
        uint4 v = *(uint4*)(stage + row * 256 + ((c16 * 16) ^ ((row & 7) << 4)));
        *(uint4*)&g_D2h[(size_t)(j0 + row) * n + i0 + c16 * 8] = v;
    }
}

// ---------------- K: alpha — pipelined W1@x + FUSED U-finalize tail ----------------
// dyn smem: Wh 0 (16K), xh 16384 (8K) -> 24576 ; grid (n/128, 32), 2 chunks
__global__ void __launch_bounds__(256) k_alpha(const float* __restrict__ x,
                                               const float* __restrict__ pr0, int n) {
    extern __shared__ char smc[];
    __shared__ unsigned int s_ticket;
    uint32_t sb = su32(smc);
    const int t = threadIdx.x, w = t >> 5, lane = t & 31;
    const int j0 = blockIdx.x * 128;
    const int ibase0 = blockIdx.y * 128;
    const float r0v = fminf(*pr0, sqrtf(__uint_as_float(g_maxbits)));
    const float R2i = 1.0f / (r0v * r0v);
    const int xrow = t >> 3, xcb = (t & 7) * 16;
    const int wj = t >> 1, wih = (t & 1) * 32;

    float C[8][4];
    #pragma unroll
    for (int b = 0; b < 8; b++)
        #pragma unroll
        for (int e = 0; e < 4; e++) C[b][e] = 0.f;

    uint4 px[2], pd[4];
    #define A_LD(ib) do { \
        px[0] = *(const uint4*)&g_xh[(size_t)((ib) + xrow) * P + xcb / 2]; \
        px[1] = *(const uint4*)&g_xh[(size_t)((ib) + 32 + xrow) * P + xcb / 2]; \
        const __half* _dr = &g_D2h[(size_t)(j0 + wj) * n + (ib) + wih]; \
        pd[0] = *(const uint4*)&_dr[0];  pd[1] = *(const uint4*)&_dr[8]; \
        pd[2] = *(const uint4*)&_dr[16]; pd[3] = *(const uint4*)&_dr[24]; \
    } while (0)

    A_LD(ibase0);
    #pragma unroll
    for (int ch = 0; ch < 2; ch++) {
        if (ch) __syncthreads();
        *(uint4*)(smc + 16384 + SWZ(xrow * 128 + xcb))        = px[0];
        *(uint4*)(smc + 16384 + SWZ((32 + xrow) * 128 + xcb)) = px[1];
        {
            float s = 0.f;
            #pragma unroll
            for (int q = 0; q < 4; q++) {
                uint32_t din[4] = {pd[q].x, pd[q].y, pd[q].z, pd[q].w};
                uint32_t hh[4];
                #pragma unroll
                for (int k = 0; k < 4; k++) {
                    float2 d2f = __half22float2(*(__half2*)&din[k]);
                    float w0 = w1f(d2f.x, R2i), w1v = w1f(d2f.y, R2i);
                    s += w0 + w1v;
                    hh[k] = packh2(w0, w1v);
                }
                *(uint4*)(smc + SWZ(wj * 128 + (wih + q * 8) * 2)) = *(uint4*)hh;
            }
            s += __shfl_xor_sync(0xffffffffu, s, 1);
            if ((t & 1) == 0) atomicAdd(&g_S1[j0 + wj], s);
        }
        if (ch == 0) A_LD(ibase0 + 64);
        __syncthreads();
        #pragma unroll
        for (int ks = 0; ks < 4; ks++) {
            int k0 = ks * 16;
            uint32_t Awh[4];
            ldm_x4(Awh, frag_addr(sb, lane, w * 16, k0));
            #pragma unroll
            for (int gq = 0; gq < 4; gq++) {
                uint32_t Bh[4];
                ldm_x4t(Bh, frag_addr(sb + 16384, lane, k0, gq * 16));
                #pragma unroll
                for (int h = 0; h < 2; h++) {
                    uint32_t bh[2] = {Bh[h * 2], Bh[h * 2 + 1]};
                    mma16816(C[gq * 2 + h], Awh, bh);
                }
            }
        }
    }
    const int g = lane >> 2, tg = lane & 3;
    #pragma unroll
    for (int ni = 0; ni < 8; ni++)
        #pragma unroll
        for (int e = 0; e < 4; e++) {
            int j = j0 + w * 16 + g + (e >> 1) * 8;
            int p = ni * 8 + tg * 2 + (e & 1);
            atomicAdd(&g_mun[(size_t)j * P + p], C[ni][e]);
        }

    // ---- fused U-finalize: last block for this j-column does k_U's work ----
    __threadfence();
    if (t == 0) s_ticket = atomicAdd(&g_cntA[blockIdx.x], 1u);
    __syncthreads();
    if (s_ticket != gridDim.y - 1) return;

    for (int r = w; r < 128; r += 8) {
        int row = j0 + r;
        float S1 = g_S1[row];
        float b = 0.f, un2 = 0.f;
        #pragma unroll
        for (int h = 0; h < 2; h++) {
            int p = lane + 32 * h;
            float mu = g_mun[(size_t)row * P + p] / S1;
            float xv = x[(size_t)row * P + p];
            if (isnan(mu)) mu = xv;
            float U = xv - mu;
            __half uh = __float2half_rn(U);
            g_Uh[(size_t)row * P + p] = uh;
            g_Ul[(size_t)row * P + p] = __float2half_rn(U - __half2float(uh));
            b += xv * U;
            un2 += U * U;
        }
        #pragma unroll
        for (int o = 16; o; o >>= 1) {
            b += __shfl_xor_sync(0xffffffffu, b, o);
            un2 += __shfl_xor_sync(0xffffffffu, un2, o);
        }
        if (lane == 0) { g_bU[row] = b; g_sU2[row] = sqrtf(un2); g_S2[row] = 0.f; }
        *(float2*)&g_accZ[(size_t)row * P + lane * 2] = make_float2(0.f, 0.f);
    }
}

// ---------------- K: beta — pipelined c-GEMM(x3) + weights + acc-GEMM(x1) + FUSED output ----------------
// dyn smem: Wh 0 (16K), Dst 16384 (16K), xh 32768 (8K), xl 40960 (8K),
//           bU 49152(512), su2 49664(512) -> 50176 ; grid (n/128, 16), 4 chunks
__global__ void __launch_bounds__(256, 2) k_beta(const float* __restrict__ x,
                                                 float* __restrict__ out,
                                                 const float* __restrict__ pr1,
                                                 const float* __restrict__ pr2, int n) {
    extern __shared__ char smc[];
    __shared__ unsigned int s_ticket;
    uint32_t sb = su32(smc);
    float* bUs  = (float*)(smc + 49152);
    float* su2s = (float*)(smc + 49664);
    const int t = threadIdx.x, w = t >> 5, lane = t & 31;
    const int j0 = blockIdx.x * 128;
    const int ibase0 = blockIdx.y * 256;
    const float md = sqrtf(__uint_as_float(g_maxbits));
    const float rr1 = fminf(*pr1, md), rr2 = fminf(*pr2, md);
    const float a1 = 2.0f / rr1, a2 = 2.0f / rr2;
    const int g = lane >> 2, tg = lane & 3;
    const int xrow = t >> 3, xcb = (t & 7) * 16;
    const int drj = t >> 3, drc = t & 7;

    for (int q = t; q < 1024; q += 256) {
        int row = q >> 3, cb = (q & 7) * 16;
        uint32_t off = SWZ(row * 128 + cb);
        *(uint4*)(smc + off)         = *(const uint4*)&g_Uh[(size_t)(j0 + row) * P + cb / 2];
        *(uint4*)(smc + 16384 + off) = *(const uint4*)&g_Ul[(size_t)(j0 + row) * P + cb / 2];
    }
    if (t < 128) { bUs[t] = g_bU[j0 + t]; su2s[t] = g_sU2[j0 + t]; }
    __syncthreads();
    uint32_t AUh[4][4], AUl[4][4];
    #pragma unroll
    for (int ks = 0; ks < 4; ks++) {
        ldm_x4(AUh[ks], frag_addr(sb,         lane, w * 16, ks * 16));
        ldm_x4(AUl[ks], frag_addr(sb + 16384, lane, w * 16, ks * 16));
    }
    __syncthreads();

    float accC[8][4];
    #pragma unroll
    for (int b = 0; b < 8; b++)
        #pragma unroll
        for (int e = 0; e < 4; e++) accC[b][e] = 0.f;

    uint4 pxh[2], pxl[2], pdq[4];
    #define B_LD(ib) do { \
        pxh[0] = *(const uint4*)&g_xh[(size_t)((ib) + xrow) * P + xcb / 2]; \
        pxl[0] = *(const uint4*)&g_xl[(size_t)((ib) + xrow) * P + xcb / 2]; \
        pxh[1] = *(const uint4*)&g_xh[(size_t)((ib) + 32 + xrow) * P + xcb / 2]; \
        pxl[1] = *(const uint4*)&g_xl[(size_t)((ib) + 32 + xrow) * P + xcb / 2]; \
        pdq[0] = *(const uint4*)&g_D2h[(size_t)(j0 + drj) * n + (ib) + drc * 8]; \
        pdq[1] = *(const uint4*)&g_D2h[(size_t)(j0 + 32 + drj) * n + (ib) + drc * 8]; \
        pdq[2] = *(const uint4*)&g_D2h[(size_t)(j0 + 64 + drj) * n + (ib) + drc * 8]; \
        pdq[3] = *(const uint4*)&g_D2h[(size_t)(j0 + 96 + drj) * n + (ib) + drc * 8]; \
    } while (0)

    B_LD(ibase0);
    #pragma unroll 1
    for (int ch = 0; ch < 4; ch++) {
        int ib = ibase0 + ch * 64;
        if (ch) __syncthreads();
        {
            uint32_t off0 = SWZ(xrow * 128 + xcb);
            uint32_t off1 = SWZ((32 + xrow) * 128 + xcb);
            *(uint4*)(smc + 32768 + off0) = pxh[0];
            *(uint4*)(smc + 40960 + off0) = pxl[0];
            *(uint4*)(smc + 32768 + off1) = pxh[1];
            *(uint4*)(smc + 40960 + off1) = pxl[1];
            #pragma unroll
            for (int m = 0; m < 4; m++) {
                int j = drj + 32 * m;
                *(uint4*)(smc + 16384 + j * 128 + ((drc * 16) ^ ((j & 7) << 4))) = pdq[m];
            }
        }
        if (ch < 3) B_LD(ib + 64);
        __syncthreads();
        float cC[8][4];
        #pragma unroll
        for (int b = 0; b < 8; b++)
            #pragma unroll
            for (int e = 0; e < 4; e++) cC[b][e] = 0.f;
        #pragma unroll
        for (int ks = 0; ks < 4; ks++) {
            int k0 = ks * 16;
            #pragma unroll
            for (int gq = 0; gq < 4; gq++) {
                uint32_t Bh[4], Bl[4];
                ldm_x4(Bh, frag_addr(sb + 32768, lane, gq * 16, k0));
                ldm_x4(Bl, frag_addr(sb + 40960, lane, gq * 16, k0));
                #pragma unroll
                for (int h = 0; h < 2; h++) {
                    int ni = gq * 2 + h;
                    uint32_t bh[2] = {Bh[h], Bh[h + 2]};
                    uint32_t bl[2] = {Bl[h], Bl[h + 2]};
                    mma16816(cC[ni], AUh[ks], bh);
                    mma16816(cC[ni], AUh[ks], bl);
                    mma16816(cC[ni], AUl[ks], bh);
                }
            }
        }
        #pragma unroll
        for (int e2 = 0; e2 < 2; e2++) {
            int jl = w * 16 + g + e2 * 8;
            float bj = bUs[jl], su2 = su2s[jl];
            float rs = 0.f;
            #pragma unroll
            for (int ni = 0; ni < 8; ni++) {
                int il = ni * 8 + tg * 2;
                float2 dd = __half22float2(
                    *(__half2*)(smc + 16384 + jl * 128 + ((il * 2) ^ ((jl & 7) << 4))));
                float wv[2], d2v[2] = {dd.x, dd.y};
                #pragma unroll
                for (int q = 0; q < 2; q++) {
                    float cp = cC[ni][e2 * 2 + q] - bj;
                    float du = fmaxf(fabsf(cp) * su2, 1e-3f);
                    float dv = asqrt(fmaxf(d2v[q] - du * du, 1e-6f));
                    wv[q] = w2f(dv, a1) * w2f(du, a2);
                }
                rs += wv[0] + wv[1];
                *(uint32_t*)(smc + SWZ(jl * 128 + il * 2)) = packh2(wv[0], wv[1]);
            }
            rs += __shfl_xor_sync(0xffffffffu, rs, 1);
            rs += __shfl_xor_sync(0xffffffffu, rs, 2);
            if (tg == 0) atomicAdd(&g_S2[j0 + jl], rs);
        }
        __syncthreads();
        #pragma unroll
        for (int ks = 0; ks < 4; ks++) {
            int k0 = ks * 16;
            uint32_t Awh[4];
            ldm_x4(Awh, frag_addr(sb, lane, w * 16, k0));
            #pragma unroll
            for (int gq = 0; gq < 4; gq++) {
                uint32_t Bh[4];
                ldm_x4t(Bh, frag_addr(sb + 32768, lane, k0, gq * 16));
                #pragma unroll
                for (int h = 0; h < 2; h++) {
                    uint32_t bh[2] = {Bh[h * 2], Bh[h * 2 + 1]};
                    mma16816(accC[gq * 2 + h], Awh, bh);
                }
            }
        }
    }
    #pragma unroll
    for (int ni = 0; ni < 8; ni++)
        #pragma unroll
        for (int e = 0; e < 4; e++) {
            int j = j0 + w * 16 + g + (e >> 1) * 8;
            int p = ni * 8 + tg * 2 + (e & 1);
            atomicAdd(&g_accZ[(size_t)j * P + p], accC[ni][e]);
        }

    // ---- fused output: last block for this j-column normalizes + stores ----
    __threadfence();
    if (t == 0) s_ticket = atomicAdd(&g_cntB[blockIdx.x], 1u);
    __syncthreads();
    if (s_ticket != gridDim.y - 1) return;

    for (int idx = t; idx < 128 * P; idx += 256) {
        int row = j0 + (idx >> 6);
        int p = idx & 63;
        float e = g_accZ[(size_t)row * P + p] / g_S2[row];
        if (isnan(e)) e = x[(size_t)row * P + p];
        out[(size_t)row * P + p] = e;
    }
}

extern "C" void kernel_launch(void* const* d_in, const int* in_sizes, int n_in,
                              void* d_out, int out_size) {
    const float* x  = (const float*)d_in[0];
    const float* r0 = (const float*)d_in[1];
    const float* r1 = (const float*)d_in[2];
    const float* r2 = (const float*)d_in[3];
    float* out = (float*)d_out;
    const int n = in_sizes[0] / P;  // 4096
    const int nb = n / 128;

    k_prep<<<(n + 7) / 8, 256>>>(x, n);

    cudaFuncSetAttribute(k_gram, cudaFuncAttributeMaxDynamicSharedMemorySize, 50176);
    k_gram<<<nb * (nb + 1) / 2, 256, 50176>>>(n);

    cudaFuncSetAttribute(k_alpha, cudaFuncAttributeMaxDynamicSharedMemorySize, 24576);
    k_alpha<<<dim3(nb, 32), 256, 24576>>>(x, r0, n);

    cudaFuncSetAttribute(k_beta, cudaFuncAttributeMaxDynamicSharedMemorySize, 50176);
    k_beta<<<dim3(nb, 16), 256, 50176>>>(x, out, r1, r2, n);
}

// round 11
// speedup vs baseline: 1.3277x; 1.3277x over previous
#include <cuda_runtime.h>
#include <cuda_fp16.h>
#include <math.h>
#include <stdint.h>

#define P 64
#define NMAX 4096

// ---------------- persistent device scratch ----------------
__device__ float g_sq[NMAX];
__device__ __half g_D2h[(size_t)NMAX * NMAX];
__device__ unsigned int g_maxbits;
__device__ float g_S1[NMAX];
__device__ float g_mun[NMAX * P];
__device__ float g_bU[NMAX];
__device__ float g_sU2[NMAX];
__device__ float g_S2[NMAX];
__device__ float g_accZ[NMAX * P];
__device__ __half g_xh[NMAX * P], g_xl[NMAX * P];
__device__ __half g_Uh[NMAX * P], g_Ul[NMAX * P];

// ---------------- helpers ----------------
__device__ __forceinline__ uint32_t su32(const void* p) {
    uint32_t a;
    asm("{ .reg .u64 t; cvta.to.shared.u64 t, %1; cvt.u32.u64 %0, t; }" : "=r"(a) : "l"(p));
    return a;
}
#define SWZ(b) ((uint32_t)(b) ^ ((((uint32_t)(b)) >> 3) & 0x70))

__device__ __forceinline__ uint32_t frag_addr(uint32_t base, int lane, int row0, int col0) {
    int r = row0 + (lane & 7) + ((lane >> 3) & 1) * 8;
    int cb = (col0 + (lane >> 4) * 8) * 2;
    return base + SWZ(r * 128 + cb);
}
__device__ __forceinline__ void ldm_x4(uint32_t* r, uint32_t a) {
    asm volatile("ldmatrix.sync.aligned.m8n8.x4.shared.b16 {%0,%1,%2,%3}, [%4];"
                 : "=r"(r[0]), "=r"(r[1]), "=r"(r[2]), "=r"(r[3]) : "r"(a));
}
__device__ __forceinline__ void ldm_x4t(uint32_t* r, uint32_t a) {
    asm volatile("ldmatrix.sync.aligned.m8n8.x4.trans.shared.b16 {%0,%1,%2,%3}, [%4];"
                 : "=r"(r[0]), "=r"(r[1]), "=r"(r[2]), "=r"(r[3]) : "r"(a));
}
__device__ __forceinline__ void mma16816(float* c, const uint32_t* a, const uint32_t* b) {
    asm volatile(
        "mma.sync.aligned.m16n8k16.row.col.f32.f16.f16.f32 "
        "{%0,%1,%2,%3}, {%4,%5,%6,%7}, {%8,%9}, {%0,%1,%2,%3};"
        : "+f"(c[0]), "+f"(c[1]), "+f"(c[2]), "+f"(c[3])
        : "r"(a[0]), "r"(a[1]), "r"(a[2]), "r"(a[3]), "r"(b[0]), "r"(b[1]));
}
__device__ __forceinline__ uint32_t packh2(float a, float b) {
    __half2 h = __floats2half2_rn(a, b);
    return *(uint32_t*)&h;
}
__device__ __forceinline__ float asqrt(float x) { float r; asm("sqrt.approx.f32 %0,%1;" : "=f"(r) : "f"(x)); return r; }
__device__ __forceinline__ float w1f(float d2, float R2i) {
    float s = fmaxf(fmaf(-d2, R2i, 1.0f), 0.0f);
    return s * s * s;
}
__device__ __forceinline__ float w2f(float d, float a) {
    float t = __saturatef(fmaf(d, a, -1.0f));
    float s = fmaf(-t, t, 1.0f);
    return s * s * s;
}

// ---------------- K: prep — sq norms + fp16 split + zero-init ----------------
__global__ void k_prep(const float* __restrict__ x, int n) {
    int gt = blockIdx.x * blockDim.x + threadIdx.x;
    int w = gt >> 5;
    int lane = threadIdx.x & 31;
    *(float2*)&g_mun[(size_t)gt * 2] = make_float2(0.f, 0.f);
    if (gt < n) g_S1[gt] = 0.f;
    if (gt == 0) g_maxbits = 0u;
    if (w >= n) return;
    float v0 = x[(size_t)w * P + lane], v1 = x[(size_t)w * P + 32 + lane];
    __half h0 = __float2half_rn(v0), h1 = __float2half_rn(v1);
    g_xh[(size_t)w * P + lane] = h0;
    g_xh[(size_t)w * P + 32 + lane] = h1;
    g_xl[(size_t)w * P + lane] = __float2half_rn(v0 - __half2float(h0));
    g_xl[(size_t)w * P + 32 + lane] = __float2half_rn(v1 - __half2float(h1));
    float s = v0 * v0 + v1 * v1;
    #pragma unroll
    for (int o = 16; o; o >>= 1) s += __shfl_xor_sync(0xffffffffu, s, o);
    if (lane == 0) g_sq[w] = s;
}

// ---------------- K: gram (upper-triangle) -> D2h, mirror store ----------------
__global__ void __launch_bounds__(256) k_gram(int n) {
    extern __shared__ char smc[];
    __shared__ float wmax[8];
    uint32_t sb = su32(smc);
    const int t = threadIdx.x, w = t >> 5, lane = t & 31;
    const int nb = n >> 7;
    int k = blockIdx.x, a = 0;
    while (k >= nb - a) { k -= nb - a; a++; }
    const int ti = a, tj = a + k;
    const int i0 = ti * 128, j0 = tj * 128;
    float* sqi = (float*)(smc + 49152);
    float* sqj = (float*)(smc + 49664);
    char* stage = smc + 16384;

    for (int q = t; q < 1024; q += 256) {
        int row = q >> 3, cb = (q & 7) * 16;
        uint32_t off = SWZ(row * 128 + cb);
        *(uint4*)(smc + off)         = *(const uint4*)&g_xh[(size_t)(i0 + row) * P + cb / 2];
        *(uint4*)(smc + 16384 + off) = *(const uint4*)&g_xh[(size_t)(j0 + row) * P + cb / 2];
        *(uint4*)(smc + 32768 + off) = *(const uint4*)&g_xl[(size_t)(j0 + row) * P + cb / 2];
    }
    if (t < 128) sqi[t] = g_sq[i0 + t];
    else sqj[t - 128] = g_sq[j0 + t - 128];
    __syncthreads();

    const int m0 = (w & 3) * 32, n0w = (w >> 2) * 64;
    float C[2][8][4];
    #pragma unroll
    for (int a2 = 0; a2 < 2; a2++)
        #pragma unroll
        for (int b = 0; b < 8; b++)
            #pragma unroll
            for (int e = 0; e < 4; e++) C[a2][b][e] = 0.f;

    #pragma unroll
    for (int ks = 0; ks < 4; ks++) {
        int k0 = ks * 16;
        uint32_t Ah[2][4];
        #pragma unroll
        for (int mi = 0; mi < 2; mi++)
            ldm_x4(Ah[mi], frag_addr(sb, lane, m0 + mi * 16, k0));
        #pragma unroll
        for (int gq = 0; gq < 4; gq++) {
            uint32_t Bh[4], Bl[4];
            ldm_x4(Bh, frag_addr(sb + 16384, lane, n0w + gq * 16, k0));
            ldm_x4(Bl, frag_addr(sb + 32768, lane, n0w + gq * 16, k0));
            #pragma unroll
            for (int h = 0; h < 2; h++) {
                int ni = gq * 2 + h;
                uint32_t bh[2] = {Bh[h], Bh[h + 2]};
                uint32_t bl[2] = {Bl[h], Bl[h + 2]};
                #pragma unroll
                for (int mi = 0; mi < 2; mi++) {
                    mma16816(C[mi][ni], Ah[mi], bh);
                    mma16816(C[mi][ni], Ah[mi], bl);
                }
            }
        }
    }
    __syncthreads();

    const int g = lane >> 2, tg = lane & 3;
    float lmax = 0.f;
    #pragma unroll
    for (int mi = 0; mi < 2; mi++)
        #pragma unroll
        for (int e2 = 0; e2 < 2; e2++) {
            int i = m0 + mi * 16 + g + e2 * 8;
            float si = sqi[i];
            #pragma unroll
            for (int ni = 0; ni < 8; ni++) {
                int j = n0w + ni * 8 + tg * 2;
                float d0 = fmaxf(si + sqj[j]     - 2.f * C[mi][ni][e2 * 2],     0.f);
                float d1 = fmaxf(si + sqj[j + 1] - 2.f * C[mi][ni][e2 * 2 + 1], 0.f);
                lmax = fmaxf(lmax, fmaxf(d0, d1));
                *(uint32_t*)(stage + i * 256 + ((j * 2) ^ ((i & 7) << 4))) = packh2(d0, d1);
            }
        }
    #pragma unroll
    for (int o = 16; o; o >>= 1) lmax = fmaxf(lmax, __shfl_xor_sync(0xffffffffu, lmax, o));
    if (lane == 0) wmax[w] = lmax;
    __syncthreads();
    if (t == 0) {
        float m = wmax[0];
        #pragma unroll
        for (int q = 1; q < 8; q++) m = fmaxf(m, wmax[q]);
        atomicMax(&g_maxbits, __float_as_uint(m));
    }
    #pragma unroll
    for (int m = 0; m < 8; m++) {
        int fi = t + 256 * m;
        int row = fi >> 4, c16 = fi & 15;
        uint4 v = *(uint4*)(stage + row * 256 + ((c16 * 16) ^ ((row & 7) << 4)));
        *(uint4*)&g_D2h[(size_t)(i0 + row) * n + j0 + c16 * 8] = v;
    }

    if (ti == tj) return;

    __syncthreads();
    #pragma unroll
    for (int mi = 0; mi < 2; mi++)
        #pragma unroll
        for (int e2 = 0; e2 < 2; e2++) {
            int i = m0 + mi * 16 + g + e2 * 8;
            float si = sqi[i];
            #pragma unroll
            for (int ni = 0; ni < 8; ni++) {
                int j = n0w + ni * 8 + tg * 2;
                float d0 = fmaxf(si + sqj[j]     - 2.f * C[mi][ni][e2 * 2],     0.f);
                float d1 = fmaxf(si + sqj[j + 1] - 2.f * C[mi][ni][e2 * 2 + 1], 0.f);
                __half h0 = __float2half_rn(d0), h1 = __float2half_rn(d1);
                *(__half*)(stage + j * 256 + ((i * 2) ^ ((j & 7) << 4)))             = h0;
                *(__half*)(stage + (j + 1) * 256 + ((i * 2) ^ (((j + 1) & 7) << 4))) = h1;
            }
        }
    __syncthreads();
    #pragma unroll
    for (int m = 0; m < 8; m++) {
        int fi = t + 256 * m;
        int row = fi >> 4, c16 = fi & 15;
        uint4 v = *(uint4*)(stage + row * 256 + ((c16 * 16) ^ ((row & 7) << 4)));
        *(uint4*)&g_D2h[(size_t)(j0 + row) * n + i0 + c16 * 8] = v;
    }
}

// ---------------- K: alpha — pipelined (register prefetch) ----------------
// dyn smem: Wh 0 (16K), xh 16384 (8K) -> 24576 ; grid (n/128, 32), 2 chunks
__global__ void __launch_bounds__(256) k_alpha(const float* __restrict__ pr0, int n) {
    extern __shared__ char smc[];
    uint32_t sb = su32(smc);
    const int t = threadIdx.x, w = t >> 5, lane = t & 31;
    const int j0 = blockIdx.x * 128;
    const int ibase0 = blockIdx.y * 128;
    const float r0v = fminf(*pr0, sqrtf(__uint_as_float(g_maxbits)));
    const float R2i = 1.0f / (r0v * r0v);
    const int xrow = t >> 3, xcb = (t & 7) * 16;
    const int wj = t >> 1, wih = (t & 1) * 32;

    float C[8][4];
    #pragma unroll
    for (int b = 0; b < 8; b++)
        #pragma unroll
        for (int e = 0; e < 4; e++) C[b][e] = 0.f;

    uint4 px[2], pd[4];
    #define A_LD(ib) do { \
        px[0] = *(const uint4*)&g_xh[(size_t)((ib) + xrow) * P + xcb / 2]; \
        px[1] = *(const uint4*)&g_xh[(size_t)((ib) + 32 + xrow) * P + xcb / 2]; \
        const __half* _dr = &g_D2h[(size_t)(j0 + wj) * n + (ib) + wih]; \
        pd[0] = *(const uint4*)&_dr[0];  pd[1] = *(const uint4*)&_dr[8]; \
        pd[2] = *(const uint4*)&_dr[16]; pd[3] = *(const uint4*)&_dr[24]; \
    } while (0)

    A_LD(ibase0);
    #pragma unroll
    for (int ch = 0; ch < 2; ch++) {
        if (ch) __syncthreads();
        *(uint4*)(smc + 16384 + SWZ(xrow * 128 + xcb))        = px[0];
        *(uint4*)(smc + 16384 + SWZ((32 + xrow) * 128 + xcb)) = px[1];
        {
            float s = 0.f;
            #pragma unroll
            for (int q = 0; q < 4; q++) {
                uint32_t din[4] = {pd[q].x, pd[q].y, pd[q].z, pd[q].w};
                uint32_t hh[4];
                #pragma unroll
                for (int k = 0; k < 4; k++) {
                    float2 d2f = __half22float2(*(__half2*)&din[k]);
                    float w0 = w1f(d2f.x, R2i), w1v = w1f(d2f.y, R2i);
                    s += w0 + w1v;
                    hh[k] = packh2(w0, w1v);
                }
                *(uint4*)(smc + SWZ(wj * 128 + (wih + q * 8) * 2)) = *(uint4*)hh;
            }
            s += __shfl_xor_sync(0xffffffffu, s, 1);
            if ((t & 1) == 0) atomicAdd(&g_S1[j0 + wj], s);
        }
        if (ch == 0) A_LD(ibase0 + 64);
        __syncthreads();
        #pragma unroll
        for (int ks = 0; ks < 4; ks++) {
            int k0 = ks * 16;
            uint32_t Awh[4];
            ldm_x4(Awh, frag_addr(sb, lane, w * 16, k0));
            #pragma unroll
            for (int gq = 0; gq < 4; gq++) {
                uint32_t Bh[4];
                ldm_x4t(Bh, frag_addr(sb + 16384, lane, k0, gq * 16));
                #pragma unroll
                for (int h = 0; h < 2; h++) {
                    uint32_t bh[2] = {Bh[h * 2], Bh[h * 2 + 1]};
                    mma16816(C[gq * 2 + h], Awh, bh);
                }
            }
        }
    }
    const int g = lane >> 2, tg = lane & 3;
    #pragma unroll
    for (int ni = 0; ni < 8; ni++)
        #pragma unroll
        for (int e = 0; e < 4; e++) {
            int j = j0 + w * 16 + g + (e >> 1) * 8;
            int p = ni * 8 + tg * 2 + (e & 1);
            atomicAdd(&g_mun[(size_t)j * P + p], C[ni][e]);
        }
}

// ---------------- K: U = x - mu (+ splits), bU, sqrt(||U||^2), zero-init ----------------
__global__ void k_U(const float* __restrict__ x, int n) {
    int gt = blockIdx.x * blockDim.x + threadIdx.x;
    int w = gt >> 5;
    int lane = threadIdx.x & 31;
    *(float2*)&g_accZ[(size_t)gt * 2] = make_float2(0.f, 0.f);
    if (gt < n) g_S2[gt] = 0.f;
    if (w >= n) return;
    float S1 = g_S1[w];
    float b = 0.f, un2 = 0.f;
    #pragma unroll
    for (int h = 0; h < 2; h++) {
        int p = lane + 32 * h;
        float mu = g_mun[(size_t)w * P + p] / S1;
        float xv = x[(size_t)w * P + p];
        if (isnan(mu)) mu = xv;
        float U = xv - mu;
        __half uh = __float2half_rn(U);
        g_Uh[(size_t)w * P + p] = uh;
        g_Ul[(size_t)w * P + p] = __float2half_rn(U - __half2float(uh));
        b += xv * U;
        un2 += U * U;
    }
    #pragma unroll
    for (int o = 16; o; o >>= 1) {
        b += __shfl_xor_sync(0xffffffffu, b, o);
        un2 += __shfl_xor_sync(0xffffffffu, un2, o);
    }
    if (lane == 0) { g_bU[w] = b; g_sU2[w] = sqrtf(un2); }
}

// ---------------- K: beta — pipelined c-GEMM(x3) + weights + acc-GEMM(x1) ----------------
// dyn smem: Wh 0 (16K), Dst 16384 (16K), xh 32768 (8K), xl 40960 (8K),
//           bU 49152(512), su2 49664(512) -> 50176 ; grid (n/128, 32), 2 chunks
__global__ void __launch_bounds__(256, 2) k_beta(const float* __restrict__ pr1,
                                                 const float* __restrict__ pr2, int n) {
    extern __shared__ char smc[];
    uint32_t sb = su32(smc);
    float* bUs  = (float*)(smc + 49152);
    float* su2s = (float*)(smc + 49664);
    const int t = threadIdx.x, w = t >> 5, lane = t & 31;
    const int j0 = blockIdx.x * 128;
    const int ibase0 = blockIdx.y * 128;
    const float md = sqrtf(__uint_as_float(g_maxbits));
    const float rr1 = fminf(*pr1, md), rr2 = fminf(*pr2, md);
    const float a1 = 2.0f / rr1, a2 = 2.0f / rr2;
    const int g = lane >> 2, tg = lane & 3;
    const int xrow = t >> 3, xcb = (t & 7) * 16;
    const int drj = t >> 3, drc = t & 7;

    for (int q = t; q < 1024; q += 256) {
        int row = q >> 3, cb = (q & 7) * 16;
        uint32_t off = SWZ(row * 128 + cb);
        *(uint4*)(smc + off)         = *(const uint4*)&g_Uh[(size_t)(j0 + row) * P + cb / 2];
        *(uint4*)(smc + 16384 + off) = *(const uint4*)&g_Ul[(size_t)(j0 + row) * P + cb / 2];
    }
    if (t < 128) { bUs[t] = g_bU[j0 + t]; su2s[t] = g_sU2[j0 + t]; }
    __syncthreads();
    uint32_t AUh[4][4], AUl[4][4];
    #pragma unroll
    for (int ks = 0; ks < 4; ks++) {
        ldm_x4(AUh[ks], frag_addr(sb,         lane, w * 16, ks * 16));
        ldm_x4(AUl[ks], frag_addr(sb + 16384, lane, w * 16, ks * 16));
    }
    __syncthreads();

    float accC[8][4];
    #pragma unroll
    for (int b = 0; b < 8; b++)
        #pragma unroll
        for (int e = 0; e < 4; e++) accC[b][e] = 0.f;

    uint4 pxh[2], pxl[2], pdq[4];
    #define B_LD(ib) do { \
        pxh[0] = *(const uint4*)&g_xh[(size_t)((ib) + xrow) * P + xcb / 2]; \
        pxl[0] = *(const uint4*)&g_xl[(size_t)((ib) + xrow) * P + xcb / 2]; \
        pxh[1] = *(const uint4*)&g_xh[(size_t)((ib) + 32 + xrow) * P + xcb / 2]; \
        pxl[1] = *(const uint4*)&g_xl[(size_t)((ib) + 32 + xrow) * P + xcb / 2]; \
        pdq[0] = *(const uint4*)&g_D2h[(size_t)(j0 + drj) * n + (ib) + drc * 8]; \
        pdq[1] = *(const uint4*)&g_D2h[(size_t)(j0 + 32 + drj) * n + (ib) + drc * 8]; \
        pdq[2] = *(const uint4*)&g_D2h[(size_t)(j0 + 64 + drj) * n + (ib) + drc * 8]; \
        pdq[3] = *(const uint4*)&g_D2h[(size_t)(j0 + 96 + drj) * n + (ib) + drc * 8]; \
    } while (0)

    B_LD(ibase0);
    #pragma unroll 1
    for (int ch = 0; ch < 2; ch++) {
        int ib = ibase0 + ch * 64;
        if (ch) __syncthreads();
        {
            uint32_t off0 = SWZ(xrow * 128 + xcb);
            uint32_t off1 = SWZ((32 + xrow) * 128 + xcb);
            *(uint4*)(smc + 32768 + off0) = pxh[0];
            *(uint4*)(smc + 40960 + off0) = pxl[0];
            *(uint4*)(smc + 32768 + off1) = pxh[1];
            *(uint4*)(smc + 40960 + off1) = pxl[1];
            #pragma unroll
            for (int m = 0; m < 4; m++) {
                int j = drj + 32 * m;
                *(uint4*)(smc + 16384 + j * 128 + ((drc * 16) ^ ((j & 7) << 4))) = pdq[m];
            }
        }
        if (ch == 0) B_LD(ib + 64);
        __syncthreads();
        float cC[8][4];
        #pragma unroll
        for (int b = 0; b < 8; b++)
            #pragma unroll
            for (int e = 0; e < 4; e++) cC[b][e] = 0.f;
        #pragma unroll
        for (int ks = 0; ks < 4; ks++) {
            int k0 = ks * 16;
            #pragma unroll
            for (int gq = 0; gq < 4; gq++) {
                uint32_t Bh[4], Bl[4];
                ldm_x4(Bh, frag_addr(sb + 32768, lane, gq * 16, k0));
                ldm_x4(Bl, frag_addr(sb + 40960, lane, gq * 16, k0));
                #pragma unroll
                for (int h = 0; h < 2; h++) {
                    int ni = gq * 2 + h;
                    uint32_t bh[2] = {Bh[h], Bh[h + 2]};
                    uint32_t bl[2] = {Bl[h], Bl[h + 2]};
                    mma16816(cC[ni], AUh[ks], bh);
                    mma16816(cC[ni], AUh[ks], bl);
                    mma16816(cC[ni], AUl[ks], bh);
                }
            }
        }
        #pragma unroll
        for (int e2 = 0; e2 < 2; e2++) {
            int jl = w * 16 + g + e2 * 8;
            float bj = bUs[jl], su2 = su2s[jl];
            float rs = 0.f;
            #pragma unroll
            for (int ni = 0; ni < 8; ni++) {
                int il = ni * 8 + tg * 2;
                float2 dd = __half22float2(
                    *(__half2*)(smc + 16384 + jl * 128 + ((il * 2) ^ ((jl & 7) << 4))));
                float wv[2], d2v[2] = {dd.x, dd.y};
                #pragma unroll
                for (int q = 0; q < 2; q++) {
                    float cp = cC[ni][e2 * 2 + q] - bj;
                    float du = fmaxf(fabsf(cp) * su2, 1e-3f);
                    float dv = asqrt(fmaxf(d2v[q] - du * du, 1e-6f));
                    wv[q] = w2f(dv, a1) * w2f(du, a2);
                }
                rs += wv[0] + wv[1];
                *(uint32_t*)(smc + SWZ(jl * 128 + il * 2)) = packh2(wv[0], wv[1]);
            }
            rs += __shfl_xor_sync(0xffffffffu, rs, 1);
            rs += __shfl_xor_sync(0xffffffffu, rs, 2);
            if (tg == 0) atomicAdd(&g_S2[j0 + jl], rs);
        }
        __syncthreads();
        #pragma unroll
        for (int ks = 0; ks < 4; ks++) {
            int k0 = ks * 16;
            uint32_t Awh[4];
            ldm_x4(Awh, frag_addr(sb, lane, w * 16, k0));
            #pragma unroll
            for (int gq = 0; gq < 4; gq++) {
                uint32_t Bh[4];
                ldm_x4t(Bh, frag_addr(sb + 32768, lane, k0, gq * 16));
                #pragma unroll
                for (int h = 0; h < 2; h++) {
                    uint32_t bh[2] = {Bh[h * 2], Bh[h * 2 + 1]};
                    mma16816(accC[gq * 2 + h], Awh, bh);
                }
            }
        }
    }
    #pragma unroll
    for (int ni = 0; ni < 8; ni++)
        #pragma unroll
        for (int e = 0; e < 4; e++) {
            int j = j0 + w * 16 + g + (e >> 1) * 8;
            int p = ni * 8 + tg * 2 + (e & 1);
            atomicAdd(&g_accZ[(size_t)j * P + p], accC[ni][e]);
        }
}

// ---------------- K: output ----------------
__global__ void k_out(const float* __restrict__ x, float* __restrict__ out, int n) {
    int idx = blockIdx.x * blockDim.x + threadIdx.x;
    if (idx >= n * P) return;
    int j = idx >> 6;
    float e = g_accZ[idx] / g_S2[j];
    if (isnan(e)) e = x[idx];
    out[idx] = e;
}

extern "C" void kernel_launch(void* const* d_in, const int* in_sizes, int n_in,
                              void* d_out, int out_size) {
    const float* x  = (const float*)d_in[0];
    const float* r0 = (const float*)d_in[1];
    const float* r1 = (const float*)d_in[2];
    const float* r2 = (const float*)d_in[3];
    float* out = (float*)d_out;
    const int n = in_sizes[0] / P;  // 4096
    const int nb = n / 128;

    k_prep<<<(n + 7) / 8, 256>>>(x, n);

    cudaFuncSetAttribute(k_gram, cudaFuncAttributeMaxDynamicSharedMemorySize, 50176);
    k_gram<<<nb * (nb + 1) / 2, 256, 50176>>>(n);

    cudaFuncSetAttribute(k_alpha, cudaFuncAttributeMaxDynamicSharedMemorySize, 24576);
    k_alpha<<<dim3(nb, 32), 256, 24576>>>(r0, n);

    k_U<<<(n + 7) / 8, 256>>>(x, n);

    cudaFuncSetAttribute(k_beta, cudaFuncAttributeMaxDynamicSharedMemorySize, 50176);
    k_beta<<<dim3(nb, 32), 256, 50176>>>(r1, r2, n);

    k_out<<<(n * P + 255) / 256, 256>>>(x, out, n);
}

// round 12
// speedup vs baseline: 1.3569x; 1.0220x over previous
#include <cuda_runtime.h>
#include <cuda_fp16.h>
#include <math.h>
#include <stdint.h>

#define P 64
#define NMAX 4096

// ---------------- persistent device scratch ----------------
__device__ float g_sq[NMAX];
__device__ __half g_D2h[(size_t)NMAX * NMAX];
__device__ unsigned int g_maxbits;
__device__ float g_S1[NMAX];
__device__ float g_mun[NMAX * P];
__device__ float g_bU[NMAX];
__device__ float g_sU2[NMAX];
__device__ float g_S2[NMAX];
__device__ float g_accZ[NMAX * P];
__device__ __half g_xh[NMAX * P], g_xl[NMAX * P];
__device__ __half g_Uh[NMAX * P], g_Ul[NMAX * P];

// ---------------- helpers ----------------
__device__ __forceinline__ uint32_t su32(const void* p) {
    uint32_t a;
    asm("{ .reg .u64 t; cvta.to.shared.u64 t, %1; cvt.u32.u64 %0, t; }" : "=r"(a) : "l"(p));
    return a;
}
#define SWZ(b) ((uint32_t)(b) ^ ((((uint32_t)(b)) >> 3) & 0x70))

__device__ __forceinline__ uint32_t frag_addr(uint32_t base, int lane, int row0, int col0) {
    int r = row0 + (lane & 7) + ((lane >> 3) & 1) * 8;
    int cb = (col0 + (lane >> 4) * 8) * 2;
    return base + SWZ(r * 128 + cb);
}
__device__ __forceinline__ void ldm_x4(uint32_t* r, uint32_t a) {
    asm volatile("ldmatrix.sync.aligned.m8n8.x4.shared.b16 {%0,%1,%2,%3}, [%4];"
                 : "=r"(r[0]), "=r"(r[1]), "=r"(r[2]), "=r"(r[3]) : "r"(a));
}
__device__ __forceinline__ void ldm_x4t(uint32_t* r, uint32_t a) {
    asm volatile("ldmatrix.sync.aligned.m8n8.x4.trans.shared.b16 {%0,%1,%2,%3}, [%4];"
                 : "=r"(r[0]), "=r"(r[1]), "=r"(r[2]), "=r"(r[3]) : "r"(a));
}
__device__ __forceinline__ void mma16816(float* c, const uint32_t* a, const uint32_t* b) {
    asm volatile(
        "mma.sync.aligned.m16n8k16.row.col.f32.f16.f16.f32 "
        "{%0,%1,%2,%3}, {%4,%5,%6,%7}, {%8,%9}, {%0,%1,%2,%3};"
        : "+f"(c[0]), "+f"(c[1]), "+f"(c[2]), "+f"(c[3])
        : "r"(a[0]), "r"(a[1]), "r"(a[2]), "r"(a[3]), "r"(b[0]), "r"(b[1]));
}
__device__ __forceinline__ uint32_t packh2(float a, float b) {
    __half2 h = __floats2half2_rn(a, b);
    return *(uint32_t*)&h;
}
__device__ __forceinline__ float asqrt(float x) { float r; asm("sqrt.approx.f32 %0,%1;" : "=f"(r) : "f"(x)); return r; }
__device__ __forceinline__ float w1f(float d2, float R2i) {
    float s = fmaxf(fmaf(-d2, R2i, 1.0f), 0.0f);
    return s * s * s;
}
__device__ __forceinline__ float w2f(float d, float a) {
    float t = __saturatef(fmaf(d, a, -1.0f));
    float s = fmaf(-t, t, 1.0f);
    return s * s * s;
}

// ---------------- K: prep — sq norms + fp16 split + ALL zero-init ----------------
__global__ void k_prep(const float* __restrict__ x, int n) {
    int gt = blockIdx.x * blockDim.x + threadIdx.x;
    int w = gt >> 5;
    int lane = threadIdx.x & 31;
    *(float2*)&g_mun[(size_t)gt * 2] = make_float2(0.f, 0.f);
    *(float2*)&g_accZ[(size_t)gt * 2] = make_float2(0.f, 0.f);
    if (gt < n) { g_S1[gt] = 0.f; g_S2[gt] = 0.f; }
    if (gt == 0) g_maxbits = 0u;
    if (w >= n) return;
    float v0 = x[(size_t)w * P + lane], v1 = x[(size_t)w * P + 32 + lane];
    __half h0 = __float2half_rn(v0), h1 = __float2half_rn(v1);
    g_xh[(size_t)w * P + lane] = h0;
    g_xh[(size_t)w * P + 32 + lane] = h1;
    g_xl[(size_t)w * P + lane] = __float2half_rn(v0 - __half2float(h0));
    g_xl[(size_t)w * P + 32 + lane] = __float2half_rn(v1 - __half2float(h1));
    float s = v0 * v0 + v1 * v1;
    #pragma unroll
    for (int o = 16; o; o >>= 1) s += __shfl_xor_sync(0xffffffffu, s, o);
    if (lane == 0) g_sq[w] = s;
}

// ---------------- K: gram (upper-triangle) -> D2h, mirror store ----------------
__global__ void __launch_bounds__(256) k_gram(int n) {
    extern __shared__ char smc[];
    __shared__ float wmax[8];
    uint32_t sb = su32(smc);
    const int t = threadIdx.x, w = t >> 5, lane = t & 31;
    const int nb = n >> 7;
    int k = blockIdx.x, a = 0;
    while (k >= nb - a) { k -= nb - a; a++; }
    const int ti = a, tj = a + k;
    const int i0 = ti * 128, j0 = tj * 128;
    float* sqi = (float*)(smc + 49152);
    float* sqj = (float*)(smc + 49664);
    char* stage = smc + 16384;

    for (int q = t; q < 1024; q += 256) {
        int row = q >> 3, cb = (q & 7) * 16;
        uint32_t off = SWZ(row * 128 + cb);
        *(uint4*)(smc + off)         = *(const uint4*)&g_xh[(size_t)(i0 + row) * P + cb / 2];
        *(uint4*)(smc + 16384 + off) = *(const uint4*)&g_xh[(size_t)(j0 + row) * P + cb / 2];
        *(uint4*)(smc + 32768 + off) = *(const uint4*)&g_xl[(size_t)(j0 + row) * P + cb / 2];
    }
    if (t < 128) sqi[t] = g_sq[i0 + t];
    else sqj[t - 128] = g_sq[j0 + t - 128];
    __syncthreads();

    const int m0 = (w & 3) * 32, n0w = (w >> 2) * 64;
    float C[2][8][4];
    #pragma unroll
    for (int a2 = 0; a2 < 2; a2++)
        #pragma unroll
        for (int b = 0; b < 8; b++)
            #pragma unroll
            for (int e = 0; e < 4; e++) C[a2][b][e] = 0.f;

    #pragma unroll
    for (int ks = 0; ks < 4; ks++) {
        int k0 = ks * 16;
        uint32_t Ah[2][4];
        #pragma unroll
        for (int mi = 0; mi < 2; mi++)
            ldm_x4(Ah[mi], frag_addr(sb, lane, m0 + mi * 16, k0));
        #pragma unroll
        for (int gq = 0; gq < 4; gq++) {
            uint32_t Bh[4], Bl[4];
            ldm_x4(Bh, frag_addr(sb + 16384, lane, n0w + gq * 16, k0));
            ldm_x4(Bl, frag_addr(sb + 32768, lane, n0w + gq * 16, k0));
            #pragma unroll
            for (int h = 0; h < 2; h++) {
                int ni = gq * 2 + h;
                uint32_t bh[2] = {Bh[h], Bh[h + 2]};
                uint32_t bl[2] = {Bl[h], Bl[h + 2]};
                #pragma unroll
                for (int mi = 0; mi < 2; mi++) {
                    mma16816(C[mi][ni], Ah[mi], bh);
                    mma16816(C[mi][ni], Ah[mi], bl);
                }
            }
        }
    }
    __syncthreads();

    const int g = lane >> 2, tg = lane & 3;
    float lmax = 0.f;
    #pragma unroll
    for (int mi = 0; mi < 2; mi++)
        #pragma unroll
        for (int e2 = 0; e2 < 2; e2++) {
            int i = m0 + mi * 16 + g + e2 * 8;
            float si = sqi[i];
            #pragma unroll
            for (int ni = 0; ni < 8; ni++) {
                int j = n0w + ni * 8 + tg * 2;
                float d0 = fmaxf(si + sqj[j]     - 2.f * C[mi][ni][e2 * 2],     0.f);
                float d1 = fmaxf(si + sqj[j + 1] - 2.f * C[mi][ni][e2 * 2 + 1], 0.f);
                lmax = fmaxf(lmax, fmaxf(d0, d1));
                *(uint32_t*)(stage + i * 256 + ((j * 2) ^ ((i & 7) << 4))) = packh2(d0, d1);
            }
        }
    #pragma unroll
    for (int o = 16; o; o >>= 1) lmax = fmaxf(lmax, __shfl_xor_sync(0xffffffffu, lmax, o));
    if (lane == 0) wmax[w] = lmax;
    __syncthreads();
    if (t == 0) {
        float m = wmax[0];
        #pragma unroll
        for (int q = 1; q < 8; q++) m = fmaxf(m, wmax[q]);
        atomicMax(&g_maxbits, __float_as_uint(m));
    }
    #pragma unroll
    for (int m = 0; m < 8; m++) {
        int fi = t + 256 * m;
        int row = fi >> 4, c16 = fi & 15;
        uint4 v = *(uint4*)(stage + row * 256 + ((c16 * 16) ^ ((row & 7) << 4)));
        *(uint4*)&g_D2h[(size_t)(i0 + row) * n + j0 + c16 * 8] = v;
    }

    if (ti == tj) return;

    __syncthreads();
    #pragma unroll
    for (int mi = 0; mi < 2; mi++)
        #pragma unroll
        for (int e2 = 0; e2 < 2; e2++) {
            int i = m0 + mi * 16 + g + e2 * 8;
            float si = sqi[i];
            #pragma unroll
            for (int ni = 0; ni < 8; ni++) {
                int j = n0w + ni * 8 + tg * 2;
                float d0 = fmaxf(si + sqj[j]     - 2.f * C[mi][ni][e2 * 2],     0.f);
                float d1 = fmaxf(si + sqj[j + 1] - 2.f * C[mi][ni][e2 * 2 + 1], 0.f);
                __half h0 = __float2half_rn(d0), h1 = __float2half_rn(d1);
                *(__half*)(stage + j * 256 + ((i * 2) ^ ((j & 7) << 4)))             = h0;
                *(__half*)(stage + (j + 1) * 256 + ((i * 2) ^ (((j + 1) & 7) << 4))) = h1;
            }
        }
    __syncthreads();
    #pragma unroll
    for (int m = 0; m < 8; m++) {
        int fi = t + 256 * m;
        int row = fi >> 4, c16 = fi & 15;
        uint4 v = *(uint4*)(stage + row * 256 + ((c16 * 16) ^ ((row & 7) << 4)));
        *(uint4*)&g_D2h[(size_t)(j0 + row) * n + i0 + c16 * 8] = v;
    }
}

// ---------------- K: alpha — pipelined (register prefetch) ----------------
// dyn smem: Wh 0 (16K), xh 16384 (8K) -> 24576 ; grid (n/128, 32), 2 chunks
__global__ void __launch_bounds__(256) k_alpha(const float* __restrict__ pr0, int n) {
    extern __shared__ char smc[];
    uint32_t sb = su32(smc);
    const int t = threadIdx.x, w = t >> 5, lane = t & 31;
    const int j0 = blockIdx.x * 128;
    const int ibase0 = blockIdx.y * 128;
    const float r0v = fminf(*pr0, sqrtf(__uint_as_float(g_maxbits)));
    const float R2i = 1.0f / (r0v * r0v);
    const int xrow = t >> 3, xcb = (t & 7) * 16;
    const int wj = t >> 1, wih = (t & 1) * 32;

    float C[8][4];
    #pragma unroll
    for (int b = 0; b < 8; b++)
        #pragma unroll
        for (int e = 0; e < 4; e++) C[b][e] = 0.f;

    uint4 px[2], pd[4];
    #define A_LD(ib) do { \
        px[0] = *(const uint4*)&g_xh[(size_t)((ib) + xrow) * P + xcb / 2]; \
        px[1] = *(const uint4*)&g_xh[(size_t)((ib) + 32 + xrow) * P + xcb / 2]; \
        const __half* _dr = &g_D2h[(size_t)(j0 + wj) * n + (ib) + wih]; \
        pd[0] = *(const uint4*)&_dr[0];  pd[1] = *(const uint4*)&_dr[8]; \
        pd[2] = *(const uint4*)&_dr[16]; pd[3] = *(const uint4*)&_dr[24]; \
    } while (0)

    A_LD(ibase0);
    #pragma unroll
    for (int ch = 0; ch < 2; ch++) {
        if (ch) __syncthreads();
        *(uint4*)(smc + 16384 + SWZ(xrow * 128 + xcb))        = px[0];
        *(uint4*)(smc + 16384 + SWZ((32 + xrow) * 128 + xcb)) = px[1];
        {
            float s = 0.f;
            #pragma unroll
            for (int q = 0; q < 4; q++) {
                uint32_t din[4] = {pd[q].x, pd[q].y, pd[q].z, pd[q].w};
                uint32_t hh[4];
                #pragma unroll
                for (int k = 0; k < 4; k++) {
                    float2 d2f = __half22float2(*(__half2*)&din[k]);
                    float w0 = w1f(d2f.x, R2i), w1v = w1f(d2f.y, R2i);
                    s += w0 + w1v;
                    hh[k] = packh2(w0, w1v);
                }
                *(uint4*)(smc + SWZ(wj * 128 + (wih + q * 8) * 2)) = *(uint4*)hh;
            }
            s += __shfl_xor_sync(0xffffffffu, s, 1);
            if ((t & 1) == 0) atomicAdd(&g_S1[j0 + wj], s);
        }
        if (ch == 0) A_LD(ibase0 + 64);
        __syncthreads();
        #pragma unroll
        for (int ks = 0; ks < 4; ks++) {
            int k0 = ks * 16;
            uint32_t Awh[4];
            ldm_x4(Awh, frag_addr(sb, lane, w * 16, k0));
            #pragma unroll
            for (int gq = 0; gq < 4; gq++) {
                uint32_t Bh[4];
                ldm_x4t(Bh, frag_addr(sb + 16384, lane, k0, gq * 16));
                #pragma unroll
                for (int h = 0; h < 2; h++) {
                    uint32_t bh[2] = {Bh[h * 2], Bh[h * 2 + 1]};
                    mma16816(C[gq * 2 + h], Awh, bh);
                }
            }
        }
    }
    const int g = lane >> 2, tg = lane & 3;
    #pragma unroll
    for (int ni = 0; ni < 8; ni++)
        #pragma unroll
        for (int e = 0; e < 4; e++) {
            int j = j0 + w * 16 + g + (e >> 1) * 8;
            int p = ni * 8 + tg * 2 + (e & 1);
            atomicAdd(&g_mun[(size_t)j * P + p], C[ni][e]);
        }
}

// ---------------- K: U — 2 rows per warp, loads batched up-front ----------------
__global__ void k_U(const float* __restrict__ x, int n) {
    int w0 = (blockIdx.x * blockDim.x + threadIdx.x) >> 5;   // 0..n/2-1
    int lane = threadIdx.x & 31;
    if (w0 >= n / 2) return;
    #pragma unroll
    for (int rr = 0; rr < 2; rr++) {
        int w = w0 + rr * (n / 2);
        float S1 = g_S1[w];
        float mu0 = g_mun[(size_t)w * P + lane];
        float mu1 = g_mun[(size_t)w * P + 32 + lane];
        float x0 = x[(size_t)w * P + lane];
        float x1 = x[(size_t)w * P + 32 + lane];
        mu0 /= S1; mu1 /= S1;
        if (isnan(mu0)) mu0 = x0;
        if (isnan(mu1)) mu1 = x1;
        float U0 = x0 - mu0, U1 = x1 - mu1;
        __half uh0 = __float2half_rn(U0), uh1 = __float2half_rn(U1);
        g_Uh[(size_t)w * P + lane] = uh0;
        g_Uh[(size_t)w * P + 32 + lane] = uh1;
        g_Ul[(size_t)w * P + lane] = __float2half_rn(U0 - __half2float(uh0));
        g_Ul[(size_t)w * P + 32 + lane] = __float2half_rn(U1 - __half2float(uh1));
        float b = x0 * U0 + x1 * U1;
        float un2 = U0 * U0 + U1 * U1;
        #pragma unroll
        for (int o = 16; o; o >>= 1) {
            b += __shfl_xor_sync(0xffffffffu, b, o);
            un2 += __shfl_xor_sync(0xffffffffu, un2, o);
        }
        if (lane == 0) { g_bU[w] = b; g_sU2[w] = sqrtf(un2); }
    }
}

// ---------------- K: beta — pipelined c-GEMM(x3) + weights + acc-GEMM(x1) ----------------
// dyn smem: Wh 0 (16K), Dst 16384 (16K), xh 32768 (8K), xl 40960 (8K),
//           bU 49152(512), su2 49664(512) -> 50176 ; grid (n/128, 16), 4 chunks
__global__ void __launch_bounds__(256, 2) k_beta(const float* __restrict__ pr1,
                                                 const float* __restrict__ pr2, int n) {
    extern __shared__ char smc[];
    uint32_t sb = su32(smc);
    float* bUs  = (float*)(smc + 49152);
    float* su2s = (float*)(smc + 49664);
    const int t = threadIdx.x, w = t >> 5, lane = t & 31;
    const int j0 = blockIdx.x * 128;
    const int ibase0 = blockIdx.y * 256;
    const float md = sqrtf(__uint_as_float(g_maxbits));
    const float rr1 = fminf(*pr1, md), rr2 = fminf(*pr2, md);
    const float a1 = 2.0f / rr1, a2 = 2.0f / rr2;
    const int g = lane >> 2, tg = lane & 3;
    const int xrow = t >> 3, xcb = (t & 7) * 16;
    const int drj = t >> 3, drc = t & 7;

    for (int q = t; q < 1024; q += 256) {
        int row = q >> 3, cb = (q & 7) * 16;
        uint32_t off = SWZ(row * 128 + cb);
        *(uint4*)(smc + off)         = *(const uint4*)&g_Uh[(size_t)(j0 + row) * P + cb / 2];
        *(uint4*)(smc + 16384 + off) = *(const uint4*)&g_Ul[(size_t)(j0 + row) * P + cb / 2];
    }
    if (t < 128) { bUs[t] = g_bU[j0 + t]; su2s[t] = g_sU2[j0 + t]; }
    __syncthreads();
    uint32_t AUh[4][4], AUl[4][4];
    #pragma unroll
    for (int ks = 0; ks < 4; ks++) {
        ldm_x4(AUh[ks], frag_addr(sb,         lane, w * 16, ks * 16));
        ldm_x4(AUl[ks], frag_addr(sb + 16384, lane, w * 16, ks * 16));
    }
    __syncthreads();

    float accC[8][4];
    #pragma unroll
    for (int b = 0; b < 8; b++)
        #pragma unroll
        for (int e = 0; e < 4; e++) accC[b][e] = 0.f;

    uint4 pxh[2], pxl[2], pdq[4];
    #define B_LD(ib) do { \
        pxh[0] = *(const uint4*)&g_xh[(size_t)((ib) + xrow) * P + xcb / 2]; \
        pxl[0] = *(const uint4*)&g_xl[(size_t)((ib) + xrow) * P + xcb / 2]; \
        pxh[1] = *(const uint4*)&g_xh[(size_t)((ib) + 32 + xrow) * P + xcb / 2]; \
        pxl[1] = *(const uint4*)&g_xl[(size_t)((ib) + 32 + xrow) * P + xcb / 2]; \
        pdq[0] = *(const uint4*)&g_D2h[(size_t)(j0 + drj) * n + (ib) + drc * 8]; \
        pdq[1] = *(const uint4*)&g_D2h[(size_t)(j0 + 32 + drj) * n + (ib) + drc * 8]; \
        pdq[2] = *(const uint4*)&g_D2h[(size_t)(j0 + 64 + drj) * n + (ib) + drc * 8]; \
        pdq[3] = *(const uint4*)&g_D2h[(size_t)(j0 + 96 + drj) * n + (ib) + drc * 8]; \
    } while (0)

    B_LD(ibase0);
    #pragma unroll 1
    for (int ch = 0; ch < 4; ch++) {
        int ib = ibase0 + ch * 64;
        if (ch) __syncthreads();
        {
            uint32_t off0 = SWZ(xrow * 128 + xcb);
            uint32_t off1 = SWZ((32 + xrow) * 128 + xcb);
            *(uint4*)(smc + 32768 + off0) = pxh[0];
            *(uint4*)(smc + 40960 + off0) = pxl[0];
            *(uint4*)(smc + 32768 + off1) = pxh[1];
            *(uint4*)(smc + 40960 + off1) = pxl[1];
            #pragma unroll
            for (int m = 0; m < 4; m++) {
                int j = drj + 32 * m;
                *(uint4*)(smc + 16384 + j * 128 + ((drc * 16) ^ ((j & 7) << 4))) = pdq[m];
            }
        }
        if (ch < 3) B_LD(ib + 64);
        __syncthreads();
        float cC[8][4];
        #pragma unroll
        for (int b = 0; b < 8; b++)
            #pragma unroll
            for (int e = 0; e < 4; e++) cC[b][e] = 0.f;
        #pragma unroll
        for (int ks = 0; ks < 4; ks++) {
            int k0 = ks * 16;
            #pragma unroll
            for (int gq = 0; gq < 4; gq++) {
                uint32_t Bh[4], Bl[4];
                ldm_x4(Bh, frag_addr(sb + 32768, lane, gq * 16, k0));
                ldm_x4(Bl, frag_addr(sb + 40960, lane, gq * 16, k0));
                #pragma unroll
                for (int h = 0; h < 2; h++) {
                    int ni = gq * 2 + h;
                    uint32_t bh[2] = {Bh[h], Bh[h + 2]};
                    uint32_t bl[2] = {Bl[h], Bl[h + 2]};
                    mma16816(cC[ni], AUh[ks], bh);
                    mma16816(cC[ni], AUh[ks], bl);
                    mma16816(cC[ni], AUl[ks], bh);
                }
            }
        }
        #pragma unroll
        for (int e2 = 0; e2 < 2; e2++) {
            int jl = w * 16 + g + e2 * 8;
            float bj = bUs[jl], su2 = su2s[jl];
            float rs = 0.f;
            #pragma unroll
            for (int ni = 0; ni < 8; ni++) {
                int il = ni * 8 + tg * 2;
                float2 dd = __half22float2(
                    *(__half2*)(smc + 16384 + jl * 128 + ((il * 2) ^ ((jl & 7) << 4))));
                float wv[2], d2v[2] = {dd.x, dd.y};
                #pragma unroll
                for (int q = 0; q < 2; q++) {
                    float cp = cC[ni][e2 * 2 + q] - bj;
                    float du = fmaxf(fabsf(cp) * su2, 1e-3f);
                    float dv = asqrt(fmaxf(d2v[q] - du * du, 1e-6f));
                    wv[q] = w2f(dv, a1) * w2f(du, a2);
                }
                rs += wv[0] + wv[1];
                *(uint32_t*)(smc + SWZ(jl * 128 + il * 2)) = packh2(wv[0], wv[1]);
            }
            rs += __shfl_xor_sync(0xffffffffu, rs, 1);
            rs += __shfl_xor_sync(0xffffffffu, rs, 2);
            if (tg == 0) atomicAdd(&g_S2[j0 + jl], rs);
        }
        __syncthreads();
        #pragma unroll
        for (int ks = 0; ks < 4; ks++) {
            int k0 = ks * 16;
            uint32_t Awh[4];
            ldm_x4(Awh, frag_addr(sb, lane, w * 16, k0));
            #pragma unroll
            for (int gq = 0; gq < 4; gq++) {
                uint32_t Bh[4];
                ldm_x4t(Bh, frag_addr(sb + 32768, lane, k0, gq * 16));
                #pragma unroll
                for (int h = 0; h < 2; h++) {
                    uint32_t bh[2] = {Bh[h * 2], Bh[h * 2 + 1]};
                    mma16816(accC[gq * 2 + h], Awh, bh);
                }
            }
        }
    }
    #pragma unroll
    for (int ni = 0; ni < 8; ni++)
        #pragma unroll
        for (int e = 0; e < 4; e++) {
            int j = j0 + w * 16 + g + (e >> 1) * 8;
            int p = ni * 8 + tg * 2 + (e & 1);
            atomicAdd(&g_accZ[(size_t)j * P + p], accC[ni][e]);
        }
}

// ---------------- K: output (float2 vectorized) ----------------
__global__ void k_out(const float* __restrict__ x, float* __restrict__ out, int n) {
    int idx = blockIdx.x * blockDim.x + threadIdx.x;   // over n*P/2
    if (idx >= n * P / 2) return;
    int j = idx >> 5;
    float S2 = g_S2[j];
    float2 acc = *(const float2*)&g_accZ[(size_t)idx * 2];
    float2 xv = *(const float2*)&x[(size_t)idx * 2];
    float e0 = acc.x / S2, e1 = acc.y / S2;
    if (isnan(e0)) e0 = xv.x;
    if (isnan(e1)) e1 = xv.y;
    *(float2*)&out[(size_t)idx * 2] = make_float2(e0, e1);
}

extern "C" void kernel_launch(void* const* d_in, const int* in_sizes, int n_in,
                              void* d_out, int out_size) {
    const float* x  = (const float*)d_in[0];
    const float* r0 = (const float*)d_in[1];
    const float* r1 = (const float*)d_in[2];
    const float* r2 = (const float*)d_in[3];
    float* out = (float*)d_out;
    const int n = in_sizes[0] / P;  // 4096
    const int nb = n / 128;

    k_prep<<<(n + 7) / 8, 256>>>(x, n);

    cudaFuncSetAttribute(k_gram, cudaFuncAttributeMaxDynamicSharedMemorySize, 50176);
    k_gram<<<nb * (nb + 1) / 2, 256, 50176>>>(n);

    cudaFuncSetAttribute(k_alpha, cudaFuncAttributeMaxDynamicSharedMemorySize, 24576);
    k_alpha<<<dim3(nb, 32), 256, 24576>>>(r0, n);

    k_U<<<(n / 2 + 7) / 8, 256>>>(x, n);

    cudaFuncSetAttribute(k_beta, cudaFuncAttributeMaxDynamicSharedMemorySize, 50176);
    k_beta<<<dim3(nb, 16), 256, 50176>>>(r1, r2, n);

    k_out<<<(n * P / 2 + 255) / 256, 256>>>(x, out, n);
}

// round 15
// speedup vs baseline: 1.4379x; 1.0597x over previous
#include <cuda_runtime.h>
#include <cuda_fp16.h>
#include <math.h>
#include <stdint.h>

#define P 64
#define NMAX 4096

// ---------------- persistent device scratch ----------------
__device__ float g_sq[NMAX];
__device__ __half g_D2h[(size_t)NMAX * NMAX];
__device__ unsigned int g_maxbits;
__device__ float g_S1[NMAX];
__device__ float g_mun[NMAX * P];
__device__ float g_bU[NMAX];
__device__ float g_sU2[NMAX];
__device__ float g_S2[NMAX];
__device__ float g_accZ[NMAX * P];
__device__ __half g_xh[NMAX * P], g_xl[NMAX * P];
__device__ __half g_Uh[NMAX * P], g_Ul[NMAX * P];

// ---------------- helpers ----------------
__device__ __forceinline__ uint32_t su32(const void* p) {
    uint32_t a;
    asm("{ .reg .u64 t; cvta.to.shared.u64 t, %1; cvt.u32.u64 %0, t; }" : "=r"(a) : "l"(p));
    return a;
}
#define SWZ(b) ((uint32_t)(b) ^ ((((uint32_t)(b)) >> 3) & 0x70))

__device__ __forceinline__ uint32_t frag_addr(uint32_t base, int lane, int row0, int col0) {
    int r = row0 + (lane & 7) + ((lane >> 3) & 1) * 8;
    int cb = (col0 + (lane >> 4) * 8) * 2;
    return base + SWZ(r * 128 + cb);
}
__device__ __forceinline__ void ldm_x4(uint32_t* r, uint32_t a) {
    asm volatile("ldmatrix.sync.aligned.m8n8.x4.shared.b16 {%0,%1,%2,%3}, [%4];"
                 : "=r"(r[0]), "=r"(r[1]), "=r"(r[2]), "=r"(r[3]) : "r"(a));
}
__device__ __forceinline__ void ldm_x4t(uint32_t* r, uint32_t a) {
    asm volatile("ldmatrix.sync.aligned.m8n8.x4.trans.shared.b16 {%0,%1,%2,%3}, [%4];"
                 : "=r"(r[0]), "=r"(r[1]), "=r"(r[2]), "=r"(r[3]) : "r"(a));
}
__device__ __forceinline__ void mma16816(float* c, const uint32_t* a, const uint32_t* b) {
    asm volatile(
        "mma.sync.aligned.m16n8k16.row.col.f32.f16.f16.f32 "
        "{%0,%1,%2,%3}, {%4,%5,%6,%7}, {%8,%9}, {%0,%1,%2,%3};"
        : "+f"(c[0]), "+f"(c[1]), "+f"(c[2]), "+f"(c[3])
        : "r"(a[0]), "r"(a[1]), "r"(a[2]), "r"(a[3]), "r"(b[0]), "r"(b[1]));
}
__device__ __forceinline__ uint32_t packh2(float a, float b) {
    __half2 h = __floats2half2_rn(a, b);
    return *(uint32_t*)&h;
}
__device__ __forceinline__ void cp16(uint32_t d, const void* s) {
    asm volatile("cp.async.cg.shared.global [%0], [%1], 16;" :: "r"(d), "l"(s));
}
#define CP_COMMIT() asm volatile("cp.async.commit_group;" ::: "memory")
#define CP_WAIT(N)  asm volatile("cp.async.wait_group %0;" :: "n"(N) : "memory")

__device__ __forceinline__ float asqrt(float x) { float r; asm("sqrt.approx.f32 %0,%1;" : "=f"(r) : "f"(x)); return r; }
__device__ __forceinline__ float w1f(float d2, float R2i) {
    float s = fmaxf(fmaf(-d2, R2i, 1.0f), 0.0f);
    return s * s * s;
}
__device__ __forceinline__ float w2f(float d, float a) {
    float t = __saturatef(fmaf(d, a, -1.0f));
    float s = fmaf(-t, t, 1.0f);
    return s * s * s;
}

// ---------------- K: prep — sq norms + fp16 split + ALL zero-init ----------------
__global__ void k_prep(const float* __restrict__ x, int n) {
    int gt = blockIdx.x * blockDim.x + threadIdx.x;
    int w = gt >> 5;
    int lane = threadIdx.x & 31;
    *(float2*)&g_mun[(size_t)gt * 2] = make_float2(0.f, 0.f);
    *(float2*)&g_accZ[(size_t)gt * 2] = make_float2(0.f, 0.f);
    if (gt < n) { g_S1[gt] = 0.f; g_S2[gt] = 0.f; }
    if (gt == 0) g_maxbits = 0u;
    if (w >= n) return;
    float v0 = x[(size_t)w * P + lane], v1 = x[(size_t)w * P + 32 + lane];
    __half h0 = __float2half_rn(v0), h1 = __float2half_rn(v1);
    g_xh[(size_t)w * P + lane] = h0;
    g_xh[(size_t)w * P + 32 + lane] = h1;
    g_xl[(size_t)w * P + lane] = __float2half_rn(v0 - __half2float(h0));
    g_xl[(size_t)w * P + 32 + lane] = __float2half_rn(v1 - __half2float(h1));
    float s = v0 * v0 + v1 * v1;
    #pragma unroll
    for (int o = 16; o; o >>= 1) s += __shfl_xor_sync(0xffffffffu, s, o);
    if (lane == 0) g_sq[w] = s;
}

// ---------------- K: gram (upper-triangle) -> D2h, mirror store ----------------
__global__ void __launch_bounds__(256) k_gram(int n) {
    extern __shared__ char smc[];
    __shared__ float wmax[8];
    uint32_t sb = su32(smc);
    const int t = threadIdx.x, w = t >> 5, lane = t & 31;
    const int nb = n >> 7;
    int k = blockIdx.x, a = 0;
    while (k >= nb - a) { k -= nb - a; a++; }
    const int ti = a, tj = a + k;
    const int i0 = ti * 128, j0 = tj * 128;
    float* sqi = (float*)(smc + 49152);
    float* sqj = (float*)(smc + 49664);
    char* stage = smc + 16384;

    for (int q = t; q < 1024; q += 256) {
        int row = q >> 3, cb = (q & 7) * 16;
        uint32_t off = SWZ(row * 128 + cb);
        *(uint4*)(smc + off)         = *(const uint4*)&g_xh[(size_t)(i0 + row) * P + cb / 2];
        *(uint4*)(smc + 16384 + off) = *(const uint4*)&g_xh[(size_t)(j0 + row) * P + cb / 2];
        *(uint4*)(smc + 32768 + off) = *(const uint4*)&g_xl[(size_t)(j0 + row) * P + cb / 2];
    }
    if (t < 128) sqi[t] = g_sq[i0 + t];
    else sqj[t - 128] = g_sq[j0 + t - 128];
    __syncthreads();

    const int m0 = (w & 3) * 32, n0w = (w >> 2) * 64;
    float C[2][8][4];
    #pragma unroll
    for (int a2 = 0; a2 < 2; a2++)
        #pragma unroll
        for (int b = 0; b < 8; b++)
            #pragma unroll
            for (int e = 0; e < 4; e++) C[a2][b][e] = 0.f;

    #pragma unroll
    for (int ks = 0; ks < 4; ks++) {
        int k0 = ks * 16;
        uint32_t Ah[2][4];
        #pragma unroll
        for (int mi = 0; mi < 2; mi++)
            ldm_x4(Ah[mi], frag_addr(sb, lane, m0 + mi * 16, k0));
        #pragma unroll
        for (int gq = 0; gq < 4; gq++) {
            uint32_t Bh[4], Bl[4];
            ldm_x4(Bh, frag_addr(sb + 16384, lane, n0w + gq * 16, k0));
            ldm_x4(Bl, frag_addr(sb + 32768, lane, n0w + gq * 16, k0));
            #pragma unroll
            for (int h = 0; h < 2; h++) {
                int ni = gq * 2 + h;
                uint32_t bh[2] = {Bh[h], Bh[h + 2]};
                uint32_t bl[2] = {Bl[h], Bl[h + 2]};
                #pragma unroll
                for (int mi = 0; mi < 2; mi++) {
                    mma16816(C[mi][ni], Ah[mi], bh);
                    mma16816(C[mi][ni], Ah[mi], bl);
                }
            }
        }
    }
    __syncthreads();

    const int g = lane >> 2, tg = lane & 3;
    float lmax = 0.f;
    #pragma unroll
    for (int mi = 0; mi < 2; mi++)
        #pragma unroll
        for (int e2 = 0; e2 < 2; e2++) {
            int i = m0 + mi * 16 + g + e2 * 8;
            float si = sqi[i];
            #pragma unroll
            for (int ni = 0; ni < 8; ni++) {
                int j = n0w + ni * 8 + tg * 2;
                float d0 = fmaxf(si + sqj[j]     - 2.f * C[mi][ni][e2 * 2],     0.f);
                float d1 = fmaxf(si + sqj[j + 1] - 2.f * C[mi][ni][e2 * 2 + 1], 0.f);
                lmax = fmaxf(lmax, fmaxf(d0, d1));
                *(uint32_t*)(stage + i * 256 + ((j * 2) ^ ((i & 7) << 4))) = packh2(d0, d1);
            }
        }
    #pragma unroll
    for (int o = 16; o; o >>= 1) lmax = fmaxf(lmax, __shfl_xor_sync(0xffffffffu, lmax, o));
    if (lane == 0) wmax[w] = lmax;
    __syncthreads();
    if (t == 0) {
        float m = wmax[0];
        #pragma unroll
        for (int q = 1; q < 8; q++) m = fmaxf(m, wmax[q]);
        atomicMax(&g_maxbits, __float_as_uint(m));
    }
    #pragma unroll
    for (int m = 0; m < 8; m++) {
        int fi = t + 256 * m;
        int row = fi >> 4, c16 = fi & 15;
        uint4 v = *(uint4*)(stage + row * 256 + ((c16 * 16) ^ ((row & 7) << 4)));
        *(uint4*)&g_D2h[(size_t)(i0 + row) * n + j0 + c16 * 8] = v;
    }

    if (ti == tj) return;

    __syncthreads();
    #pragma unroll
    for (int mi = 0; mi < 2; mi++)
        #pragma unroll
        for (int e2 = 0; e2 < 2; e2++) {
            int i = m0 + mi * 16 + g + e2 * 8;
            float si = sqi[i];
            #pragma unroll
            for (int ni = 0; ni < 8; ni++) {
                int j = n0w + ni * 8 + tg * 2;
                float d0 = fmaxf(si + sqj[j]     - 2.f * C[mi][ni][e2 * 2],     0.f);
                float d1 = fmaxf(si + sqj[j + 1] - 2.f * C[mi][ni][e2 * 2 + 1], 0.f);
                __half h0 = __float2half_rn(d0), h1 = __float2half_rn(d1);
                *(__half*)(stage + j * 256 + ((i * 2) ^ ((j & 7) << 4)))             = h0;
                *(__half*)(stage + (j + 1) * 256 + ((i * 2) ^ (((j + 1) & 7) << 4))) = h1;
            }
        }
    __syncthreads();
    #pragma unroll
    for (int m = 0; m < 8; m++) {
        int fi = t + 256 * m;
        int row = fi >> 4, c16 = fi & 15;
        uint4 v = *(uint4*)(stage + row * 256 + ((c16 * 16) ^ ((row & 7) << 4)));
        *(uint4*)&g_D2h[(size_t)(j0 + row) * n + i0 + c16 * 8] = v;
    }
}

// ---------------- K: alpha — pipelined (register prefetch) ----------------
// dyn smem: Wh 0 (16K), xh 16384 (8K) -> 24576 ; grid (n/128, 32), 2 chunks
__global__ void __launch_bounds__(256) k_alpha(const float* __restrict__ pr0, int n) {
    extern __shared__ char smc[];
    uint32_t sb = su32(smc);
    const int t = threadIdx.x, w = t >> 5, lane = t & 31;
    const int j0 = blockIdx.x * 128;
    const int ibase0 = blockIdx.y * 128;
    const float r0v = fminf(*pr0, sqrtf(__uint_as_float(g_maxbits)));
    const float R2i = 1.0f / (r0v * r0v);
    const int xrow = t >> 3, xcb = (t & 7) * 16;
    const int wj = t >> 1, wih = (t & 1) * 32;

    float C[8][4];
    #pragma unroll
    for (int b = 0; b < 8; b++)
        #pragma unroll
        for (int e = 0; e < 4; e++) C[b][e] = 0.f;

    uint4 px[2], pd[4];
    #define A_LD(ib) do { \
        px[0] = *(const uint4*)&g_xh[(size_t)((ib) + xrow) * P + xcb / 2]; \
        px[1] = *(const uint4*)&g_xh[(size_t)((ib) + 32 + xrow) * P + xcb / 2]; \
        const __half* _dr = &g_D2h[(size_t)(j0 + wj) * n + (ib) + wih]; \
        pd[0] = *(const uint4*)&_dr[0];  pd[1] = *(const uint4*)&_dr[8]; \
        pd[2] = *(const uint4*)&_dr[16]; pd[3] = *(const uint4*)&_dr[24]; \
    } while (0)

    A_LD(ibase0);
    #pragma unroll
    for (int ch = 0; ch < 2; ch++) {
        if (ch) __syncthreads();
        *(uint4*)(smc + 16384 + SWZ(xrow * 128 + xcb))        = px[0];
        *(uint4*)(smc + 16384 + SWZ((32 + xrow) * 128 + xcb)) = px[1];
        {
            float s = 0.f;
            #pragma unroll
            for (int q = 0; q < 4; q++) {
                uint32_t din[4] = {pd[q].x, pd[q].y, pd[q].z, pd[q].w};
                uint32_t hh[4];
                #pragma unroll
                for (int k = 0; k < 4; k++) {
                    float2 d2f = __half22float2(*(__half2*)&din[k]);
                    float w0 = w1f(d2f.x, R2i), w1v = w1f(d2f.y, R2i);
                    s += w0 + w1v;
                    hh[k] = packh2(w0, w1v);
                }
                *(uint4*)(smc + SWZ(wj * 128 + (wih + q * 8) * 2)) = *(uint4*)hh;
            }
            s += __shfl_xor_sync(0xffffffffu, s, 1);
            if ((t & 1) == 0) atomicAdd(&g_S1[j0 + wj], s);
        }
        if (ch == 0) A_LD(ibase0 + 64);
        __syncthreads();
        #pragma unroll
        for (int ks = 0; ks < 4; ks++) {
            int k0 = ks * 16;
            uint32_t Awh[4];
            ldm_x4(Awh, frag_addr(sb, lane, w * 16, k0));
            #pragma unroll
            for (int gq = 0; gq < 4; gq++) {
                uint32_t Bh[4];
                ldm_x4t(Bh, frag_addr(sb + 16384, lane, k0, gq * 16));
                #pragma unroll
                for (int h = 0; h < 2; h++) {
                    uint32_t bh[2] = {Bh[h * 2], Bh[h * 2 + 1]};
                    mma16816(C[gq * 2 + h], Awh, bh);
                }
            }
        }
    }
    const int g = lane >> 2, tg = lane & 3;
    #pragma unroll
    for (int ni = 0; ni < 8; ni++)
        #pragma unroll
        for (int e = 0; e < 4; e++) {
            int j = j0 + w * 16 + g + (e >> 1) * 8;
            int p = ni * 8 + tg * 2 + (e & 1);
            atomicAdd(&g_mun[(size_t)j * P + p], C[ni][e]);
        }
}

// ---------------- K: U — 2 rows per warp ----------------
__global__ void k_U(const float* __restrict__ x, int n) {
    int w0 = (blockIdx.x * blockDim.x + threadIdx.x) >> 5;
    int lane = threadIdx.x & 31;
    if (w0 >= n / 2) return;
    #pragma unroll
    for (int rr = 0; rr < 2; rr++) {
        int w = w0 + rr * (n / 2);
        float S1 = g_S1[w];
        float mu0 = g_mun[(size_t)w * P + lane];
        float mu1 = g_mun[(size_t)w * P + 32 + lane];
        float x0 = x[(size_t)w * P + lane];
        float x1 = x[(size_t)w * P + 32 + lane];
        mu0 /= S1; mu1 /= S1;
        if (isnan(mu0)) mu0 = x0;
        if (isnan(mu1)) mu1 = x1;
        float U0 = x0 - mu0, U1 = x1 - mu1;
        __half uh0 = __float2half_rn(U0), uh1 = __float2half_rn(U1);
        g_Uh[(size_t)w * P + lane] = uh0;
        g_Uh[(size_t)w * P + 32 + lane] = uh1;
        g_Ul[(size_t)w * P + lane] = __float2half_rn(U0 - __half2float(uh0));
        g_Ul[(size_t)w * P + 32 + lane] = __float2half_rn(U1 - __half2float(uh1));
        float b = x0 * U0 + x1 * U1;
        float un2 = U0 * U0 + U1 * U1;
        #pragma unroll
        for (int o = 16; o; o >>= 1) {
            b += __shfl_xor_sync(0xffffffffu, b, o);
            un2 += __shfl_xor_sync(0xffffffffu, un2, o);
        }
        if (lane == 0) { g_bU[w] = b; g_sU2[w] = sqrtf(un2); }
    }
}

// ---------------- K: beta — cp.async x-tiles (double buffer) + reg-prefetch D2 ----------------
// dyn smem: Wh 0 (16K), DST 16384 (16K), XB0 32768 (xh 8K + xl 8K), XB1 49152 (16K),
//           bU 65536(512), su2 66048(512) -> 66560 ; grid (n/128, 16), 4 chunks
// cp.async schedule: preload chunk0->XB0 (G0), chunk1->XB1 (G1); at top of chunk ch
// (ch=1,2) issue chunk ch+1 -> XB[(ch+1)&1] (safe: that buffer's readers finished in
// chunk ch-1, retired by the top-of-loop sync); per chunk wait_group 1 (last: 0).
__global__ void __launch_bounds__(256, 2) k_beta(const float* __restrict__ pr1,
                                                 const float* __restrict__ pr2, int n) {
    extern __shared__ char smc[];
    uint32_t sb = su32(smc);
    float* bUs  = (float*)(smc + 65536);
    float* su2s = (float*)(smc + 66048);
    const int t = threadIdx.x, w = t >> 5, lane = t & 31;
    const int j0 = blockIdx.x * 128;
    const int ibase0 = blockIdx.y * 256;
    const float md = sqrtf(__uint_as_float(g_maxbits));
    const float rr1 = fminf(*pr1, md), rr2 = fminf(*pr2, md);
    const float a1 = 2.0f / rr1, a2 = 2.0f / rr2;
    const int g = lane >> 2, tg = lane & 3;
    const int xrow = t >> 3, xcb = (t & 7) * 16;
    const int drj = t >> 3, drc = t & 7;

    #define CPX(bbase, ib) do { \
        uint32_t _o0 = SWZ(xrow * 128 + xcb), _o1 = SWZ((32 + xrow) * 128 + xcb); \
        cp16((bbase) + _o0,        &g_xh[(size_t)((ib) + xrow) * P + xcb / 2]); \
        cp16((bbase) + _o1,        &g_xh[(size_t)((ib) + 32 + xrow) * P + xcb / 2]); \
        cp16((bbase) + 8192 + _o0, &g_xl[(size_t)((ib) + xrow) * P + xcb / 2]); \
        cp16((bbase) + 8192 + _o1, &g_xl[(size_t)((ib) + 32 + xrow) * P + xcb / 2]); \
    } while (0)
    uint4 pdq[4];
    #define B_LDD(ib) do { \
        pdq[0] = *(const uint4*)&g_D2h[(size_t)(j0 + drj) * n + (ib) + drc * 8]; \
        pdq[1] = *(const uint4*)&g_D2h[(size_t)(j0 + 32 + drj) * n + (ib) + drc * 8]; \
        pdq[2] = *(const uint4*)&g_D2h[(size_t)(j0 + 64 + drj) * n + (ib) + drc * 8]; \
        pdq[3] = *(const uint4*)&g_D2h[(size_t)(j0 + 96 + drj) * n + (ib) + drc * 8]; \
    } while (0)

    // preload: chunk0 -> XB0 (G0); chunk1 -> XB1 (G1); D2 chunk0 -> regs
    CPX(sb + 32768, ibase0);
    CP_COMMIT();
    CPX(sb + 49152, ibase0 + 64);
    CP_COMMIT();
    B_LDD(ibase0);

    // stage U hi/lo, cache A fragments
    for (int q = t; q < 1024; q += 256) {
        int row = q >> 3, cb = (q & 7) * 16;
        uint32_t off = SWZ(row * 128 + cb);
        *(uint4*)(smc + off)         = *(const uint4*)&g_Uh[(size_t)(j0 + row) * P + cb / 2];
        *(uint4*)(smc + 16384 + off) = *(const uint4*)&g_Ul[(size_t)(j0 + row) * P + cb / 2];
    }
    if (t < 128) { bUs[t] = g_bU[j0 + t]; su2s[t] = g_sU2[j0 + t]; }
    __syncthreads();
    uint32_t AUh[4][4], AUl[4][4];
    #pragma unroll
    for (int ks = 0; ks < 4; ks++) {
        ldm_x4(AUh[ks], frag_addr(sb,         lane, w * 16, ks * 16));
        ldm_x4(AUl[ks], frag_addr(sb + 16384, lane, w * 16, ks * 16));
    }
    __syncthreads();   // all DST (Ul) reads complete before DST is reused for D2

    float accC[8][4];
    #pragma unroll
    for (int b = 0; b < 8; b++)
        #pragma unroll
        for (int e = 0; e < 4; e++) accC[b][e] = 0.f;

    #pragma unroll 1
    for (int ch = 0; ch < 4; ch++) {
        int ib = ibase0 + ch * 64;
        if (ch) __syncthreads();   // retires chunk ch-1's reads of XB[(ch+1)&1] and DST
        // store D2 regs -> DST
        #pragma unroll
        for (int m = 0; m < 4; m++) {
            int j = drj + 32 * m;
            *(uint4*)(smc + 16384 + j * 128 + ((drc * 16) ^ ((j & 7) << 4))) = pdq[m];
        }
        // issue next x chunk (ch+1) into its (now free) buffer
        if (ch >= 1 && ch <= 2) { CPX(sb + 32768 + ((ch + 1) & 1) * 16384, ibase0 + (ch + 1) * 64); CP_COMMIT(); }
        // prefetch next D2 into regs (overlaps c-GEMM)
        if (ch < 3) B_LDD(ib + 64);
        if (ch < 3) CP_WAIT(1); else CP_WAIT(0);
        __syncthreads();
        uint32_t xbh = sb + 32768 + (ch & 1) * 16384;
        uint32_t xbl = xbh + 8192;

        float cC[8][4];
        #pragma unroll
        for (int b = 0; b < 8; b++)
            #pragma unroll
            for (int e = 0; e < 4; e++) cC[b][e] = 0.f;
        #pragma unroll
        for (int ks = 0; ks < 4; ks++) {
            int k0 = ks * 16;
            #pragma unroll
            for (int gq = 0; gq < 4; gq++) {
                uint32_t Bh[4], Bl[4];
                ldm_x4(Bh, frag_addr(xbh, lane, gq * 16, k0));
                ldm_x4(Bl, frag_addr(xbl, lane, gq * 16, k0));
                #pragma unroll
                for (int h = 0; h < 2; h++) {
                    int ni = gq * 2 + h;
                    uint32_t bh[2] = {Bh[h], Bh[h + 2]};
                    uint32_t bl[2] = {Bl[h], Bl[h + 2]};
                    mma16816(cC[ni], AUh[ks], bh);
                    mma16816(cC[ni], AUh[ks], bl);
                    mma16816(cC[ni], AUl[ks], bh);
                }
            }
        }
        #pragma unroll
        for (int e2 = 0; e2 < 2; e2++) {
            int jl = w * 16 + g + e2 * 8;
            float bj = bUs[jl], su2 = su2s[jl];
            float rs = 0.f;
            #pragma unroll
            for (int ni = 0; ni < 8; ni++) {
                int il = ni * 8 + tg * 2;
                float2 dd = __half22float2(
                    *(__half2*)(smc + 16384 + jl * 128 + ((il * 2) ^ ((jl & 7) << 4))));
                float wv[2], d2v[2] = {dd.x, dd.y};
                #pragma unroll
                for (int q = 0; q < 2; q++) {
                    float cp = cC[ni][e2 * 2 + q] - bj;
                    float du = fmaxf(fabsf(cp) * su2, 1e-3f);
                    float dv = asqrt(fmaxf(d2v[q] - du * du, 1e-6f));
                    wv[q] = w2f(dv, a1) * w2f(du, a2);
                }
                rs += wv[0] + wv[1];
                *(uint32_t*)(smc + SWZ(jl * 128 + il * 2)) = packh2(wv[0], wv[1]);
            }
            rs += __shfl_xor_sync(0xffffffffu, rs, 1);
            rs += __shfl_xor_sync(0xffffffffu, rs, 2);
            if (tg == 0) atomicAdd(&g_S2[j0 + jl], rs);
        }
        __syncthreads();
        #pragma unroll
        for (int ks = 0; ks < 4; ks++) {
            int k0 = ks * 16;
            uint32_t Awh[4];
            ldm_x4(Awh, frag_addr(sb, lane, w * 16, k0));
            #pragma unroll
            for (int gq = 0; gq < 4; gq++) {
                uint32_t Bh[4];
                ldm_x4t(Bh, frag_addr(xbh, lane, k0, gq * 16));
                #pragma unroll
                for (int h = 0; h < 2; h++) {
                    uint32_t bh[2] = {Bh[h * 2], Bh[h * 2 + 1]};
                    mma16816(accC[gq * 2 + h], Awh, bh);
                }
            }
        }
    }
    #pragma unroll
    for (int ni = 0; ni < 8; ni++)
        #pragma unroll
        for (int e = 0; e < 4; e++) {
            int j = j0 + w * 16 + g + (e >> 1) * 8;
            int p = ni * 8 + tg * 2 + (e & 1);
            atomicAdd(&g_accZ[(size_t)j * P + p], accC[ni][e]);
        }
}

// ---------------- K: output (float2 vectorized) ----------------
__global__ void k_out(const float* __restrict__ x, float* __restrict__ out, int n) {
    int idx = blockIdx.x * blockDim.x + threadIdx.x;
    if (idx >= n * P / 2) return;
    int j = idx >> 5;
    float S2 = g_S2[j];
    float2 acc = *(const float2*)&g_accZ[(size_t)idx * 2];
    float2 xv = *(const float2*)&x[(size_t)idx * 2];
    float e0 = acc.x / S2, e1 = acc.y / S2;
    if (isnan(e0)) e0 = xv.x;
    if (isnan(e1)) e1 = xv.y;
    *(float2*)&out[(size_t)idx * 2] = make_float2(e0, e1);
}

extern "C" void kernel_launch(void* const* d_in, const int* in_sizes, int n_in,
                              void* d_out, int out_size) {
    const float* x  = (const float*)d_in[0];
    const float* r0 = (const float*)d_in[1];
    const float* r1 = (const float*)d_in[2];
    const float* r2 = (const float*)d_in[3];
    float* out = (float*)d_out;
    const int n = in_sizes[0] / P;  // 4096
    const int nb = n / 128;

    k_prep<<<(n + 7) / 8, 256>>>(x, n);

    cudaFuncSetAttribute(k_gram, cudaFuncAttributeMaxDynamicSharedMemorySize, 50176);
    k_gram<<<nb * (nb + 1) / 2, 256, 50176>>>(n);

    cudaFuncSetAttribute(k_alpha, cudaFuncAttributeMaxDynamicSharedMemorySize, 24576);
    k_alpha<<<dim3(nb, 32), 256, 24576>>>(r0, n);

    k_U<<<(n / 2 + 7) / 8, 256>>>(x, n);

    cudaFuncSetAttribute(k_beta, cudaFuncAttributeMaxDynamicSharedMemorySize, 66560);
    k_beta<<<dim3(nb, 16), 256, 66560>>>(r1, r2, n);

    k_out<<<(n * P / 2 + 255) / 256, 256>>>(x, out, n);
}

// round 16
// speedup vs baseline: 1.4667x; 1.0200x over previous
#include <cuda_runtime.h>
#include <cuda_fp16.h>
#include <math.h>
#include <stdint.h>

#define P 64
#define NMAX 4096

// ---------------- persistent device scratch ----------------
__device__ float g_sq[NMAX];
__device__ __half g_D2h[(size_t)NMAX * NMAX];
__device__ unsigned int g_maxbits;
__device__ float g_S1[NMAX];
__device__ float g_mun[NMAX * P];
__device__ float g_bU[NMAX];
__device__ float g_sU2[NMAX];
__device__ float g_S2[NMAX];
__device__ float g_accZ[NMAX * P];
__device__ __half g_xh[NMAX * P], g_xl[NMAX * P];
__device__ __half g_Uh[NMAX * P], g_Ul[NMAX * P];

// ---------------- helpers ----------------
__device__ __forceinline__ uint32_t su32(const void* p) {
    uint32_t a;
    asm("{ .reg .u64 t; cvta.to.shared.u64 t, %1; cvt.u32.u64 %0, t; }" : "=r"(a) : "l"(p));
    return a;
}
#define SWZ(b) ((uint32_t)(b) ^ ((((uint32_t)(b)) >> 3) & 0x70))

__device__ __forceinline__ uint32_t frag_addr(uint32_t base, int lane, int row0, int col0) {
    int r = row0 + (lane & 7) + ((lane >> 3) & 1) * 8;
    int cb = (col0 + (lane >> 4) * 8) * 2;
    return base + SWZ(r * 128 + cb);
}
__device__ __forceinline__ void ldm_x4(uint32_t* r, uint32_t a) {
    asm volatile("ldmatrix.sync.aligned.m8n8.x4.shared.b16 {%0,%1,%2,%3}, [%4];"
                 : "=r"(r[0]), "=r"(r[1]), "=r"(r[2]), "=r"(r[3]) : "r"(a));
}
__device__ __forceinline__ void ldm_x4t(uint32_t* r, uint32_t a) {
    asm volatile("ldmatrix.sync.aligned.m8n8.x4.trans.shared.b16 {%0,%1,%2,%3}, [%4];"
                 : "=r"(r[0]), "=r"(r[1]), "=r"(r[2]), "=r"(r[3]) : "r"(a));
}
__device__ __forceinline__ void mma16816(float* c, const uint32_t* a, const uint32_t* b) {
    asm volatile(
        "mma.sync.aligned.m16n8k16.row.col.f32.f16.f16.f32 "
        "{%0,%1,%2,%3}, {%4,%5,%6,%7}, {%8,%9}, {%0,%1,%2,%3};"
        : "+f"(c[0]), "+f"(c[1]), "+f"(c[2]), "+f"(c[3])
        : "r"(a[0]), "r"(a[1]), "r"(a[2]), "r"(a[3]), "r"(b[0]), "r"(b[1]));
}
__device__ __forceinline__ uint32_t packh2(float a, float b) {
    __half2 h = __floats2half2_rn(a, b);
    return *(uint32_t*)&h;
}
__device__ __forceinline__ void cp16(uint32_t d, const void* s) {
    asm volatile("cp.async.cg.shared.global [%0], [%1], 16;" :: "r"(d), "l"(s));
}
#define CP_COMMIT() asm volatile("cp.async.commit_group;" ::: "memory")
#define CP_WAIT(N)  asm volatile("cp.async.wait_group %0;" :: "n"(N) : "memory")

__device__ __forceinline__ float asqrt(float x) { float r; asm("sqrt.approx.f32 %0,%1;" : "=f"(r) : "f"(x)); return r; }
__device__ __forceinline__ float w1f(float d2, float R2i) {
    float s = fmaxf(fmaf(-d2, R2i, 1.0f), 0.0f);
    return s * s * s;
}
__device__ __forceinline__ float w2f(float d, float a) {
    float t = __saturatef(fmaf(d, a, -1.0f));
    float s = fmaf(-t, t, 1.0f);
    return s * s * s;
}

// ---------------- K: prep — sq norms + fp16 split + ALL zero-init ----------------
__global__ void k_prep(const float* __restrict__ x, int n) {
    int gt = blockIdx.x * blockDim.x + threadIdx.x;
    int w = gt >> 5;
    int lane = threadIdx.x & 31;
    *(float2*)&g_mun[(size_t)gt * 2] = make_float2(0.f, 0.f);
    *(float2*)&g_accZ[(size_t)gt * 2] = make_float2(0.f, 0.f);
    if (gt < n) { g_S1[gt] = 0.f; g_S2[gt] = 0.f; }
    if (gt == 0) g_maxbits = 0u;
    if (w >= n) return;
    float v0 = x[(size_t)w * P + lane], v1 = x[(size_t)w * P + 32 + lane];
    __half h0 = __float2half_rn(v0), h1 = __float2half_rn(v1);
    g_xh[(size_t)w * P + lane] = h0;
    g_xh[(size_t)w * P + 32 + lane] = h1;
    g_xl[(size_t)w * P + lane] = __float2half_rn(v0 - __half2float(h0));
    g_xl[(size_t)w * P + 32 + lane] = __float2half_rn(v1 - __half2float(h1));
    float s = v0 * v0 + v1 * v1;
    #pragma unroll
    for (int o = 16; o; o >>= 1) s += __shfl_xor_sync(0xffffffffu, s, o);
    if (lane == 0) g_sq[w] = s;
}

// ---------------- K: gram (upper-triangle) -> D2h, mirror store (cp.async loads) ----------------
__global__ void __launch_bounds__(256) k_gram(int n) {
    extern __shared__ char smc[];
    __shared__ float wmax[8];
    uint32_t sb = su32(smc);
    const int t = threadIdx.x, w = t >> 5, lane = t & 31;
    const int nb = n >> 7;
    int k = blockIdx.x, a = 0;
    while (k >= nb - a) { k -= nb - a; a++; }
    const int ti = a, tj = a + k;
    const int i0 = ti * 128, j0 = tj * 128;
    float* sqi = (float*)(smc + 49152);
    float* sqj = (float*)(smc + 49664);
    char* stage = smc + 16384;

    for (int q = t; q < 1024; q += 256) {
        int row = q >> 3, cb = (q & 7) * 16;
        uint32_t off = SWZ(row * 128 + cb);
        cp16(sb + off,         &g_xh[(size_t)(i0 + row) * P + cb / 2]);
        cp16(sb + 16384 + off, &g_xh[(size_t)(j0 + row) * P + cb / 2]);
        cp16(sb + 32768 + off, &g_xl[(size_t)(j0 + row) * P + cb / 2]);
    }
    CP_COMMIT();
    if (t < 128) sqi[t] = g_sq[i0 + t];
    else sqj[t - 128] = g_sq[j0 + t - 128];
    CP_WAIT(0);
    __syncthreads();

    const int m0 = (w & 3) * 32, n0w = (w >> 2) * 64;
    float C[2][8][4];
    #pragma unroll
    for (int a2 = 0; a2 < 2; a2++)
        #pragma unroll
        for (int b = 0; b < 8; b++)
            #pragma unroll
            for (int e = 0; e < 4; e++) C[a2][b][e] = 0.f;

    #pragma unroll
    for (int ks = 0; ks < 4; ks++) {
        int k0 = ks * 16;
        uint32_t Ah[2][4];
        #pragma unroll
        for (int mi = 0; mi < 2; mi++)
            ldm_x4(Ah[mi], frag_addr(sb, lane, m0 + mi * 16, k0));
        #pragma unroll
        for (int gq = 0; gq < 4; gq++) {
            uint32_t Bh[4], Bl[4];
            ldm_x4(Bh, frag_addr(sb + 16384, lane, n0w + gq * 16, k0));
            ldm_x4(Bl, frag_addr(sb + 32768, lane, n0w + gq * 16, k0));
            #pragma unroll
            for (int h = 0; h < 2; h++) {
                int ni = gq * 2 + h;
                uint32_t bh[2] = {Bh[h], Bh[h + 2]};
                uint32_t bl[2] = {Bl[h], Bl[h + 2]};
                #pragma unroll
                for (int mi = 0; mi < 2; mi++) {
                    mma16816(C[mi][ni], Ah[mi], bh);
                    mma16816(C[mi][ni], Ah[mi], bl);
                }
            }
        }
    }
    __syncthreads();

    const int g = lane >> 2, tg = lane & 3;
    float lmax = 0.f;
    #pragma unroll
    for (int mi = 0; mi < 2; mi++)
        #pragma unroll
        for (int e2 = 0; e2 < 2; e2++) {
            int i = m0 + mi * 16 + g + e2 * 8;
            float si = sqi[i];
            #pragma unroll
            for (int ni = 0; ni < 8; ni++) {
                int j = n0w + ni * 8 + tg * 2;
                float d0 = fmaxf(si + sqj[j]     - 2.f * C[mi][ni][e2 * 2],     0.f);
                float d1 = fmaxf(si + sqj[j + 1] - 2.f * C[mi][ni][e2 * 2 + 1], 0.f);
                lmax = fmaxf(lmax, fmaxf(d0, d1));
                *(uint32_t*)(stage + i * 256 + ((j * 2) ^ ((i & 7) << 4))) = packh2(d0, d1);
            }
        }
    #pragma unroll
    for (int o = 16; o; o >>= 1) lmax = fmaxf(lmax, __shfl_xor_sync(0xffffffffu, lmax, o));
    if (lane == 0) wmax[w] = lmax;
    __syncthreads();
    if (t == 0) {
        float m = wmax[0];
        #pragma unroll
        for (int q = 1; q < 8; q++) m = fmaxf(m, wmax[q]);
        atomicMax(&g_maxbits, __float_as_uint(m));
    }
    #pragma unroll
    for (int m = 0; m < 8; m++) {
        int fi = t + 256 * m;
        int row = fi >> 4, c16 = fi & 15;
        uint4 v = *(uint4*)(stage + row * 256 + ((c16 * 16) ^ ((row & 7) << 4)));
        *(uint4*)&g_D2h[(size_t)(i0 + row) * n + j0 + c16 * 8] = v;
    }

    if (ti == tj) return;

    __syncthreads();
    #pragma unroll
    for (int mi = 0; mi < 2; mi++)
        #pragma unroll
        for (int e2 = 0; e2 < 2; e2++) {
            int i = m0 + mi * 16 + g + e2 * 8;
            float si = sqi[i];
            #pragma unroll
            for (int ni = 0; ni < 8; ni++) {
                int j = n0w + ni * 8 + tg * 2;
                float d0 = fmaxf(si + sqj[j]     - 2.f * C[mi][ni][e2 * 2],     0.f);
                float d1 = fmaxf(si + sqj[j + 1] - 2.f * C[mi][ni][e2 * 2 + 1], 0.f);
                __half h0 = __float2half_rn(d0), h1 = __float2half_rn(d1);
                *(__half*)(stage + j * 256 + ((i * 2) ^ ((j & 7) << 4)))             = h0;
                *(__half*)(stage + (j + 1) * 256 + ((i * 2) ^ (((j + 1) & 7) << 4))) = h1;
            }
        }
    __syncthreads();
    #pragma unroll
    for (int m = 0; m < 8; m++) {
        int fi = t + 256 * m;
        int row = fi >> 4, c16 = fi & 15;
        uint4 v = *(uint4*)(stage + row * 256 + ((c16 * 16) ^ ((row & 7) << 4)));
        *(uint4*)&g_D2h[(size_t)(j0 + row) * n + i0 + c16 * 8] = v;
    }
}

// ---------------- K: alpha — cp.async x double-buffer + reg-prefetch D2 ----------------
// dyn smem: Wh 0 (16K), XA0 16384 (8K), XA1 24576 (8K) -> 32768 ; grid (n/128, 32), 2 chunks
__global__ void __launch_bounds__(256) k_alpha(const float* __restrict__ pr0, int n) {
    extern __shared__ char smc[];
    uint32_t sb = su32(smc);
    const int t = threadIdx.x, w = t >> 5, lane = t & 31;
    const int j0 = blockIdx.x * 128;
    const int ibase0 = blockIdx.y * 128;
    const float r0v = fminf(*pr0, sqrtf(__uint_as_float(g_maxbits)));
    const float R2i = 1.0f / (r0v * r0v);
    const int xrow = t >> 3, xcb = (t & 7) * 16;
    const int wj = t >> 1, wih = (t & 1) * 32;

    float C[8][4];
    #pragma unroll
    for (int b = 0; b < 8; b++)
        #pragma unroll
        for (int e = 0; e < 4; e++) C[b][e] = 0.f;

    // cp.async x (xh only), 64 rows: 2 x uint4 per thread
    #define CPA(bbase, ib) do { \
        cp16((bbase) + SWZ(xrow * 128 + xcb),        &g_xh[(size_t)((ib) + xrow) * P + xcb / 2]); \
        cp16((bbase) + SWZ((32 + xrow) * 128 + xcb), &g_xh[(size_t)((ib) + 32 + xrow) * P + xcb / 2]); \
    } while (0)
    uint4 pd[4];
    #define A_LDD(ib) do { \
        const __half* _dr = &g_D2h[(size_t)(j0 + wj) * n + (ib) + wih]; \
        pd[0] = *(const uint4*)&_dr[0];  pd[1] = *(const uint4*)&_dr[8]; \
        pd[2] = *(const uint4*)&_dr[16]; pd[3] = *(const uint4*)&_dr[24]; \
    } while (0)

    CPA(sb + 16384, ibase0);       // chunk0 -> XA0 (G0)
    CP_COMMIT();
    CPA(sb + 24576, ibase0 + 64);  // chunk1 -> XA1 (G1)
    CP_COMMIT();
    A_LDD(ibase0);

    #pragma unroll
    for (int ch = 0; ch < 2; ch++) {
        if (ch) __syncthreads();
        // weight-gen from D2 registers -> Wh
        {
            float s = 0.f;
            #pragma unroll
            for (int q = 0; q < 4; q++) {
                uint32_t din[4] = {pd[q].x, pd[q].y, pd[q].z, pd[q].w};
                uint32_t hh[4];
                #pragma unroll
                for (int k = 0; k < 4; k++) {
                    float2 d2f = __half22float2(*(__half2*)&din[k]);
                    float w0 = w1f(d2f.x, R2i), w1v = w1f(d2f.y, R2i);
                    s += w0 + w1v;
                    hh[k] = packh2(w0, w1v);
                }
                *(uint4*)(smc + SWZ(wj * 128 + (wih + q * 8) * 2)) = *(uint4*)hh;
            }
            s += __shfl_xor_sync(0xffffffffu, s, 1);
            if ((t & 1) == 0) atomicAdd(&g_S1[j0 + wj], s);
        }
        if (ch == 0) A_LDD(ibase0 + 64);
        if (ch == 0) CP_WAIT(1); else CP_WAIT(0);
        __syncthreads();
        uint32_t xab = sb + 16384 + ch * 8192;
        #pragma unroll
        for (int ks = 0; ks < 4; ks++) {
            int k0 = ks * 16;
            uint32_t Awh[4];
            ldm_x4(Awh, frag_addr(sb, lane, w * 16, k0));
            #pragma unroll
            for (int gq = 0; gq < 4; gq++) {
                uint32_t Bh[4];
                ldm_x4t(Bh, frag_addr(xab, lane, k0, gq * 16));
                #pragma unroll
                for (int h = 0; h < 2; h++) {
                    uint32_t bh[2] = {Bh[h * 2], Bh[h * 2 + 1]};
                    mma16816(C[gq * 2 + h], Awh, bh);
                }
            }
        }
    }
    const int g = lane >> 2, tg = lane & 3;
    #pragma unroll
    for (int ni = 0; ni < 8; ni++)
        #pragma unroll
        for (int e = 0; e < 4; e++) {
            int j = j0 + w * 16 + g + (e >> 1) * 8;
            int p = ni * 8 + tg * 2 + (e & 1);
            atomicAdd(&g_mun[(size_t)j * P + p], C[ni][e]);
        }
}

// ---------------- K: U — 2 rows per warp ----------------
__global__ void k_U(const float* __restrict__ x, int n) {
    int w0 = (blockIdx.x * blockDim.x + threadIdx.x) >> 5;
    int lane = threadIdx.x & 31;
    if (w0 >= n / 2) return;
    #pragma unroll
    for (int rr = 0; rr < 2; rr++) {
        int w = w0 + rr * (n / 2);
        float S1 = g_S1[w];
        float mu0 = g_mun[(size_t)w * P + lane];
        float mu1 = g_mun[(size_t)w * P + 32 + lane];
        float x0 = x[(size_t)w * P + lane];
        float x1 = x[(size_t)w * P + 32 + lane];
        mu0 /= S1; mu1 /= S1;
        if (isnan(mu0)) mu0 = x0;
        if (isnan(mu1)) mu1 = x1;
        float U0 = x0 - mu0, U1 = x1 - mu1;
        __half uh0 = __float2half_rn(U0), uh1 = __float2half_rn(U1);
        g_Uh[(size_t)w * P + lane] = uh0;
        g_Uh[(size_t)w * P + 32 + lane] = uh1;
        g_Ul[(size_t)w * P + lane] = __float2half_rn(U0 - __half2float(uh0));
        g_Ul[(size_t)w * P + 32 + lane] = __float2half_rn(U1 - __half2float(uh1));
        float b = x0 * U0 + x1 * U1;
        float un2 = U0 * U0 + U1 * U1;
        #pragma unroll
        for (int o = 16; o; o >>= 1) {
            b += __shfl_xor_sync(0xffffffffu, b, o);
            un2 += __shfl_xor_sync(0xffffffffu, un2, o);
        }
        if (lane == 0) { g_bU[w] = b; g_sU2[w] = sqrtf(un2); }
    }
}

// ---------------- K: beta — cp.async x-tiles (double buffer) + reg-prefetch D2 ----------------
// dyn smem: Wh 0 (16K), DST 16384 (16K), XB0 32768 (xh 8K + xl 8K), XB1 49152 (16K),
//           bU 65536(512), su2 66048(512) -> 66560 ; grid (n/128, 16), 4 chunks
__global__ void __launch_bounds__(256, 2) k_beta(const float* __restrict__ pr1,
                                                 const float* __restrict__ pr2, int n) {
    extern __shared__ char smc[];
    uint32_t sb = su32(smc);
    float* bUs  = (float*)(smc + 65536);
    float* su2s = (float*)(smc + 66048);
    const int t = threadIdx.x, w = t >> 5, lane = t & 31;
    const int j0 = blockIdx.x * 128;
    const int ibase0 = blockIdx.y * 256;
    const float md = sqrtf(__uint_as_float(g_maxbits));
    const float rr1 = fminf(*pr1, md), rr2 = fminf(*pr2, md);
    const float a1 = 2.0f / rr1, a2 = 2.0f / rr2;
    const int g = lane >> 2, tg = lane & 3;
    const int xrow = t >> 3, xcb = (t & 7) * 16;
    const int drj = t >> 3, drc = t & 7;

    #define CPX(bbase, ib) do { \
        uint32_t _o0 = SWZ(xrow * 128 + xcb), _o1 = SWZ((32 + xrow) * 128 + xcb); \
        cp16((bbase) + _o0,        &g_xh[(size_t)((ib) + xrow) * P + xcb / 2]); \
        cp16((bbase) + _o1,        &g_xh[(size_t)((ib) + 32 + xrow) * P + xcb / 2]); \
        cp16((bbase) + 8192 + _o0, &g_xl[(size_t)((ib) + xrow) * P + xcb / 2]); \
        cp16((bbase) + 8192 + _o1, &g_xl[(size_t)((ib) + 32 + xrow) * P + xcb / 2]); \
    } while (0)
    uint4 pdq[4];
    #define B_LDD(ib) do { \
        pdq[0] = *(const uint4*)&g_D2h[(size_t)(j0 + drj) * n + (ib) + drc * 8]; \
        pdq[1] = *(const uint4*)&g_D2h[(size_t)(j0 + 32 + drj) * n + (ib) + drc * 8]; \
        pdq[2] = *(const uint4*)&g_D2h[(size_t)(j0 + 64 + drj) * n + (ib) + drc * 8]; \
        pdq[3] = *(const uint4*)&g_D2h[(size_t)(j0 + 96 + drj) * n + (ib) + drc * 8]; \
    } while (0)

    CPX(sb + 32768, ibase0);
    CP_COMMIT();
    CPX(sb + 49152, ibase0 + 64);
    CP_COMMIT();
    B_LDD(ibase0);

    for (int q = t; q < 1024; q += 256) {
        int row = q >> 3, cb = (q & 7) * 16;
        uint32_t off = SWZ(row * 128 + cb);
        *(uint4*)(smc + off)         = *(const uint4*)&g_Uh[(size_t)(j0 + row) * P + cb / 2];
        *(uint4*)(smc + 16384 + off) = *(const uint4*)&g_Ul[(size_t)(j0 + row) * P + cb / 2];
    }
    if (t < 128) { bUs[t] = g_bU[j0 + t]; su2s[t] = g_sU2[j0 + t]; }
    __syncthreads();
    uint32_t AUh[4][4], AUl[4][4];
    #pragma unroll
    for (int ks = 0; ks < 4; ks++) {
        ldm_x4(AUh[ks], frag_addr(sb,         lane, w * 16, ks * 16));
        ldm_x4(AUl[ks], frag_addr(sb + 16384, lane, w * 16, ks * 16));
    }
    __syncthreads();

    float accC[8][4];
    #pragma unroll
    for (int b = 0; b < 8; b++)
        #pragma unroll
        for (int e = 0; e < 4; e++) accC[b][e] = 0.f;

    #pragma unroll 1
    for (int ch = 0; ch < 4; ch++) {
        int ib = ibase0 + ch * 64;
        if (ch) __syncthreads();
        #pragma unroll
        for (int m = 0; m < 4; m++) {
            int j = drj + 32 * m;
            *(uint4*)(smc + 16384 + j * 128 + ((drc * 16) ^ ((j & 7) << 4))) = pdq[m];
        }
        if (ch >= 1 && ch <= 2) { CPX(sb + 32768 + ((ch + 1) & 1) * 16384, ibase0 + (ch + 1) * 64); CP_COMMIT(); }
        if (ch < 3) B_LDD(ib + 64);
        if (ch < 3) CP_WAIT(1); else CP_WAIT(0);
        __syncthreads();
        uint32_t xbh = sb + 32768 + (ch & 1) * 16384;
        uint32_t xbl = xbh + 8192;

        float cC[8][4];
        #pragma unroll
        for (int b = 0; b < 8; b++)
            #pragma unroll
            for (int e = 0; e < 4; e++) cC[b][e] = 0.f;
        #pragma unroll
        for (int ks = 0; ks < 4; ks++) {
            int k0 = ks * 16;
            #pragma unroll
            for (int gq = 0; gq < 4; gq++) {
                uint32_t Bh[4], Bl[4];
                ldm_x4(Bh, frag_addr(xbh, lane, gq * 16, k0));
                ldm_x4(Bl, frag_addr(xbl, lane, gq * 16, k0));
                #pragma unroll
                for (int h = 0; h < 2; h++) {
                    int ni = gq * 2 + h;
                    uint32_t bh[2] = {Bh[h], Bh[h + 2]};
                    uint32_t bl[2] = {Bl[h], Bl[h + 2]};
                    mma16816(cC[ni], AUh[ks], bh);
                    mma16816(cC[ni], AUh[ks], bl);
                    mma16816(cC[ni], AUl[ks], bh);
                }
            }
        }
        #pragma unroll
        for (int e2 = 0; e2 < 2; e2++) {
            int jl = w * 16 + g + e2 * 8;
            float bj = bUs[jl], su2 = su2s[jl];
            float rs = 0.f;
            #pragma unroll
            for (int ni = 0; ni < 8; ni++) {
                int il = ni * 8 + tg * 2;
                float2 dd = __half22float2(
                    *(__half2*)(smc + 16384 + jl * 128 + ((il * 2) ^ ((jl & 7) << 4))));
                float wv[2], d2v[2] = {dd.x, dd.y};
                #pragma unroll
                for (int q = 0; q < 2; q++) {
                    float cp = cC[ni][e2 * 2 + q] - bj;
                    float du = fmaxf(fabsf(cp) * su2, 1e-3f);
                    float dv = asqrt(fmaxf(d2v[q] - du * du, 1e-6f));
                    wv[q] = w2f(dv, a1) * w2f(du, a2);
                }
                rs += wv[0] + wv[1];
                *(uint32_t*)(smc + SWZ(jl * 128 + il * 2)) = packh2(wv[0], wv[1]);
            }
            rs += __shfl_xor_sync(0xffffffffu, rs, 1);
            rs += __shfl_xor_sync(0xffffffffu, rs, 2);
            if (tg == 0) atomicAdd(&g_S2[j0 + jl], rs);
        }
        __syncthreads();
        #pragma unroll
        for (int ks = 0; ks < 4; ks++) {
            int k0 = ks * 16;
            uint32_t Awh[4];
            ldm_x4(Awh, frag_addr(sb, lane, w * 16, k0));
            #pragma unroll
            for (int gq = 0; gq < 4; gq++) {
                uint32_t Bh[4];
                ldm_x4t(Bh, frag_addr(xbh, lane, k0, gq * 16));
                #pragma unroll
                for (int h = 0; h < 2; h++) {
                    uint32_t bh[2] = {Bh[h * 2], Bh[h * 2 + 1]};
                    mma16816(accC[gq * 2 + h], Awh, bh);
                }
            }
        }
    }
    #pragma unroll
    for (int ni = 0; ni < 8; ni++)
        #pragma unroll
        for (int e = 0; e < 4; e++) {
            int j = j0 + w * 16 + g + (e >> 1) * 8;
            int p = ni * 8 + tg * 2 + (e & 1);
            atomicAdd(&g_accZ[(size_t)j * P + p], accC[ni][e]);
        }
}

// ---------------- K: output (float2 vectorized) ----------------
__global__ void k_out(const float* __restrict__ x, float* __restrict__ out, int n) {
    int idx = blockIdx.x * blockDim.x + threadIdx.x;
    if (idx >= n * P / 2) return;
    int j = idx >> 5;
    float S2 = g_S2[j];
    float2 acc = *(const float2*)&g_accZ[(size_t)idx * 2];
    float2 xv = *(const float2*)&x[(size_t)idx * 2];
    float e0 = acc.x / S2, e1 = acc.y / S2;
    if (isnan(e0)) e0 = xv.x;
    if (isnan(e1)) e1 = xv.y;
    *(float2*)&out[(size_t)idx * 2] = make_float2(e0, e1);
}

extern "C" void kernel_launch(void* const* d_in, const int* in_sizes, int n_in,
                              void* d_out, int out_size) {
    const float* x  = (const float*)d_in[0];
    const float* r0 = (const float*)d_in[1];
    const float* r1 = (const float*)d_in[2];
    const float* r2 = (const float*)d_in[3];
    float* out = (float*)d_out;
    const int n = in_sizes[0] / P;  // 4096
    const int nb = n / 128;

    k_prep<<<(n + 7) / 8, 256>>>(x, n);

    cudaFuncSetAttribute(k_gram, cudaFuncAttributeMaxDynamicSharedMemorySize, 50176);
    k_gram<<<nb * (nb + 1) / 2, 256, 50176>>>(n);

    cudaFuncSetAttribute(k_alpha, cudaFuncAttributeMaxDynamicSharedMemorySize, 32768);
    k_alpha<<<dim3(nb, 32), 256, 32768>>>(r0, n);

    k_U<<<(n / 2 + 7) / 8, 256>>>(x, n);

    cudaFuncSetAttribute(k_beta, cudaFuncAttributeMaxDynamicSharedMemorySize, 66560);
    k_beta<<<dim3(nb, 16), 256, 66560>>>(r1, r2, n);

    k_out<<<(n * P / 2 + 255) / 256, 256>>>(x, out, n);
}

// round 17
// speedup vs baseline: 1.5618x; 1.0649x over previous
#include <cuda_runtime.h>
#include <cuda_fp16.h>
#include <math.h>
#include <stdint.h>

#define P 64
#define NMAX 4096

// ---------------- persistent device scratch ----------------
__device__ float g_sq[NMAX];
__device__ __half g_D2h[(size_t)NMAX * NMAX];
__device__ unsigned int g_maxbits;
__device__ float g_S1[NMAX];
__device__ float g_mun[NMAX * P];
__device__ float g_bU[NMAX];
__device__ float g_sU2[NMAX];
__device__ float g_S2[NMAX];
__device__ float g_accZ[NMAX * P];
__device__ __half g_xh[NMAX * P], g_xl[NMAX * P];
__device__ __half g_Uh[NMAX * P];

// ---------------- helpers ----------------
__device__ __forceinline__ uint32_t su32(const void* p) {
    uint32_t a;
    asm("{ .reg .u64 t; cvta.to.shared.u64 t, %1; cvt.u32.u64 %0, t; }" : "=r"(a) : "l"(p));
    return a;
}
#define SWZ(b) ((uint32_t)(b) ^ ((((uint32_t)(b)) >> 3) & 0x70))

__device__ __forceinline__ uint32_t frag_addr(uint32_t base, int lane, int row0, int col0) {
    int r = row0 + (lane & 7) + ((lane >> 3) & 1) * 8;
    int cb = (col0 + (lane >> 4) * 8) * 2;
    return base + SWZ(r * 128 + cb);
}
__device__ __forceinline__ void ldm_x4(uint32_t* r, uint32_t a) {
    asm volatile("ldmatrix.sync.aligned.m8n8.x4.shared.b16 {%0,%1,%2,%3}, [%4];"
                 : "=r"(r[0]), "=r"(r[1]), "=r"(r[2]), "=r"(r[3]) : "r"(a));
}
__device__ __forceinline__ void ldm_x4t(uint32_t* r, uint32_t a) {
    asm volatile("ldmatrix.sync.aligned.m8n8.x4.trans.shared.b16 {%0,%1,%2,%3}, [%4];"
                 : "=r"(r[0]), "=r"(r[1]), "=r"(r[2]), "=r"(r[3]) : "r"(a));
}
__device__ __forceinline__ void mma16816(float* c, const uint32_t* a, const uint32_t* b) {
    asm volatile(
        "mma.sync.aligned.m16n8k16.row.col.f32.f16.f16.f32 "
        "{%0,%1,%2,%3}, {%4,%5,%6,%7}, {%8,%9}, {%0,%1,%2,%3};"
        : "+f"(c[0]), "+f"(c[1]), "+f"(c[2]), "+f"(c[3])
        : "r"(a[0]), "r"(a[1]), "r"(a[2]), "r"(a[3]), "r"(b[0]), "r"(b[1]));
}
__device__ __forceinline__ uint32_t packh2(float a, float b) {
    __half2 h = __floats2half2_rn(a, b);
    return *(uint32_t*)&h;
}
__device__ __forceinline__ void cp16(uint32_t d, const void* s) {
    asm volatile("cp.async.cg.shared.global [%0], [%1], 16;" :: "r"(d), "l"(s));
}
#define CP_COMMIT() asm volatile("cp.async.commit_group;" ::: "memory")
#define CP_WAIT(N)  asm volatile("cp.async.wait_group %0;" :: "n"(N) : "memory")

__device__ __forceinline__ float asqrt(float x) { float r; asm("sqrt.approx.f32 %0,%1;" : "=f"(r) : "f"(x)); return r; }
__device__ __forceinline__ float w1f(float d2, float R2i) {
    float s = fmaxf(fmaf(-d2, R2i, 1.0f), 0.0f);
    return s * s * s;
}
__device__ __forceinline__ float w2f(float d, float a) {
    float t = __saturatef(fmaf(d, a, -1.0f));
    float s = fmaf(-t, t, 1.0f);
    return s * s * s;
}

// ---------------- K: prep — sq norms + fp16 split + ALL zero-init ----------------
__global__ void k_prep(const float* __restrict__ x, int n) {
    int gt = blockIdx.x * blockDim.x + threadIdx.x;
    int w = gt >> 5;
    int lane = threadIdx.x & 31;
    *(float2*)&g_mun[(size_t)gt * 2] = make_float2(0.f, 0.f);
    *(float2*)&g_accZ[(size_t)gt * 2] = make_float2(0.f, 0.f);
    if (gt < n) { g_S1[gt] = 0.f; g_S2[gt] = 0.f; }
    if (gt == 0) g_maxbits = 0u;
    if (w >= n) return;
    float v0 = x[(size_t)w * P + lane], v1 = x[(size_t)w * P + 32 + lane];
    __half h0 = __float2half_rn(v0), h1 = __float2half_rn(v1);
    g_xh[(size_t)w * P + lane] = h0;
    g_xh[(size_t)w * P + 32 + lane] = h1;
    g_xl[(size_t)w * P + lane] = __float2half_rn(v0 - __half2float(h0));
    g_xl[(size_t)w * P + 32 + lane] = __float2half_rn(v1 - __half2float(h1));
    float s = v0 * v0 + v1 * v1;
    #pragma unroll
    for (int o = 16; o; o >>= 1) s += __shfl_xor_sync(0xffffffffu, s, o);
    if (lane == 0) g_sq[w] = s;
}

// ---------------- K: gram (upper-triangle) -> D2h, mirror store (cp.async loads) ----------------
__global__ void __launch_bounds__(256) k_gram(int n) {
    extern __shared__ char smc[];
    __shared__ float wmax[8];
    uint32_t sb = su32(smc);
    const int t = threadIdx.x, w = t >> 5, lane = t & 31;
    const int nb = n >> 7;
    int k = blockIdx.x, a = 0;
    while (k >= nb - a) { k -= nb - a; a++; }
    const int ti = a, tj = a + k;
    const int i0 = ti * 128, j0 = tj * 128;
    float* sqi = (float*)(smc + 49152);
    float* sqj = (float*)(smc + 49664);
    char* stage = smc + 16384;

    for (int q = t; q < 1024; q += 256) {
        int row = q >> 3, cb = (q & 7) * 16;
        uint32_t off = SWZ(row * 128 + cb);
        cp16(sb + off,         &g_xh[(size_t)(i0 + row) * P + cb / 2]);
        cp16(sb + 16384 + off, &g_xh[(size_t)(j0 + row) * P + cb / 2]);
        cp16(sb + 32768 + off, &g_xl[(size_t)(j0 + row) * P + cb / 2]);
    }
    CP_COMMIT();
    if (t < 128) sqi[t] = g_sq[i0 + t];
    else sqj[t - 128] = g_sq[j0 + t - 128];
    CP_WAIT(0);
    __syncthreads();

    const int m0 = (w & 3) * 32, n0w = (w >> 2) * 64;
    float C[2][8][4];
    #pragma unroll
    for (int a2 = 0; a2 < 2; a2++)
        #pragma unroll
        for (int b = 0; b < 8; b++)
            #pragma unroll
            for (int e = 0; e < 4; e++) C[a2][b][e] = 0.f;

    #pragma unroll
    for (int ks = 0; ks < 4; ks++) {
        int k0 = ks * 16;
        uint32_t Ah[2][4];
        #pragma unroll
        for (int mi = 0; mi < 2; mi++)
            ldm_x4(Ah[mi], frag_addr(sb, lane, m0 + mi * 16, k0));
        #pragma unroll
        for (int gq = 0; gq < 4; gq++) {
            uint32_t Bh[4], Bl[4];
            ldm_x4(Bh, frag_addr(sb + 16384, lane, n0w + gq * 16, k0));
            ldm_x4(Bl, frag_addr(sb + 32768, lane, n0w + gq * 16, k0));
            #pragma unroll
            for (int h = 0; h < 2; h++) {
                int ni = gq * 2 + h;
                uint32_t bh[2] = {Bh[h], Bh[h + 2]};
                uint32_t bl[2] = {Bl[h], Bl[h + 2]};
                #pragma unroll
                for (int mi = 0; mi < 2; mi++) {
                    mma16816(C[mi][ni], Ah[mi], bh);
                    mma16816(C[mi][ni], Ah[mi], bl);
                }
            }
        }
    }
    __syncthreads();

    const int g = lane >> 2, tg = lane & 3;
    float lmax = 0.f;
    #pragma unroll
    for (int mi = 0; mi < 2; mi++)
        #pragma unroll
        for (int e2 = 0; e2 < 2; e2++) {
            int i = m0 + mi * 16 + g + e2 * 8;
            float si = sqi[i];
            #pragma unroll
            for (int ni = 0; ni < 8; ni++) {
                int j = n0w + ni * 8 + tg * 2;
                float d0 = fmaxf(si + sqj[j]     - 2.f * C[mi][ni][e2 * 2],     0.f);
                float d1 = fmaxf(si + sqj[j + 1] - 2.f * C[mi][ni][e2 * 2 + 1], 0.f);
                lmax = fmaxf(lmax, fmaxf(d0, d1));
                *(uint32_t*)(stage + i * 256 + ((j * 2) ^ ((i & 7) << 4))) = packh2(d0, d1);
            }
        }
    #pragma unroll
    for (int o = 16; o; o >>= 1) lmax = fmaxf(lmax, __shfl_xor_sync(0xffffffffu, lmax, o));
    if (lane == 0) wmax[w] = lmax;
    __syncthreads();
    if (t == 0) {
        float m = wmax[0];
        #pragma unroll
        for (int q = 1; q < 8; q++) m = fmaxf(m, wmax[q]);
        atomicMax(&g_maxbits, __float_as_uint(m));
    }
    #pragma unroll
    for (int m = 0; m < 8; m++) {
        int fi = t + 256 * m;
        int row = fi >> 4, c16 = fi & 15;
        uint4 v = *(uint4*)(stage + row * 256 + ((c16 * 16) ^ ((row & 7) << 4)));
        *(uint4*)&g_D2h[(size_t)(i0 + row) * n + j0 + c16 * 8] = v;
    }

    if (ti == tj) return;

    __syncthreads();
    #pragma unroll
    for (int mi = 0; mi < 2; mi++)
        #pragma unroll
        for (int e2 = 0; e2 < 2; e2++) {
            int i = m0 + mi * 16 + g + e2 * 8;
            float si = sqi[i];
            #pragma unroll
            for (int ni = 0; ni < 8; ni++) {
                int j = n0w + ni * 8 + tg * 2;
                float d0 = fmaxf(si + sqj[j]     - 2.f * C[mi][ni][e2 * 2],     0.f);
                float d1 = fmaxf(si + sqj[j + 1] - 2.f * C[mi][ni][e2 * 2 + 1], 0.f);
                __half h0 = __float2half_rn(d0), h1 = __float2half_rn(d1);
                *(__half*)(stage + j * 256 + ((i * 2) ^ ((j & 7) << 4)))             = h0;
                *(__half*)(stage + (j + 1) * 256 + ((i * 2) ^ (((j + 1) & 7) << 4))) = h1;
            }
        }
    __syncthreads();
    #pragma unroll
    for (int m = 0; m < 8; m++) {
        int fi = t + 256 * m;
        int row = fi >> 4, c16 = fi & 15;
        uint4 v = *(uint4*)(stage + row * 256 + ((c16 * 16) ^ ((row & 7) << 4)));
        *(uint4*)&g_D2h[(size_t)(j0 + row) * n + i0 + c16 * 8] = v;
    }
}

// ---------------- K: alpha — cp.async x double-buffer + reg-prefetch D2 ----------------
// dyn smem: Wh 0 (16K), XA0 16384 (8K), XA1 24576 (8K) -> 32768 ; grid (n/128, 32), 2 chunks
__global__ void __launch_bounds__(256) k_alpha(const float* __restrict__ pr0, int n) {
    extern __shared__ char smc[];
    uint32_t sb = su32(smc);
    const int t = threadIdx.x, w = t >> 5, lane = t & 31;
    const int j0 = blockIdx.x * 128;
    const int ibase0 = blockIdx.y * 128;
    const float r0v = fminf(*pr0, sqrtf(__uint_as_float(g_maxbits)));
    const float R2i = 1.0f / (r0v * r0v);
    const int xrow = t >> 3, xcb = (t & 7) * 16;
    const int wj = t >> 1, wih = (t & 1) * 32;

    float C[8][4];
    #pragma unroll
    for (int b = 0; b < 8; b++)
        #pragma unroll
        for (int e = 0; e < 4; e++) C[b][e] = 0.f;

    #define CPA(bbase, ib) do { \
        cp16((bbase) + SWZ(xrow * 128 + xcb),        &g_xh[(size_t)((ib) + xrow) * P + xcb / 2]); \
        cp16((bbase) + SWZ((32 + xrow) * 128 + xcb), &g_xh[(size_t)((ib) + 32 + xrow) * P + xcb / 2]); \
    } while (0)
    uint4 pd[4];
    #define A_LDD(ib) do { \
        const __half* _dr = &g_D2h[(size_t)(j0 + wj) * n + (ib) + wih]; \
        pd[0] = *(const uint4*)&_dr[0];  pd[1] = *(const uint4*)&_dr[8]; \
        pd[2] = *(const uint4*)&_dr[16]; pd[3] = *(const uint4*)&_dr[24]; \
    } while (0)

    CPA(sb + 16384, ibase0);
    CP_COMMIT();
    CPA(sb + 24576, ibase0 + 64);
    CP_COMMIT();
    A_LDD(ibase0);

    #pragma unroll
    for (int ch = 0; ch < 2; ch++) {
        if (ch) __syncthreads();
        {
            float s = 0.f;
            #pragma unroll
            for (int q = 0; q < 4; q++) {
                uint32_t din[4] = {pd[q].x, pd[q].y, pd[q].z, pd[q].w};
                uint32_t hh[4];
                #pragma unroll
                for (int k = 0; k < 4; k++) {
                    float2 d2f = __half22float2(*(__half2*)&din[k]);
                    float w0 = w1f(d2f.x, R2i), w1v = w1f(d2f.y, R2i);
                    s += w0 + w1v;
                    hh[k] = packh2(w0, w1v);
                }
                *(uint4*)(smc + SWZ(wj * 128 + (wih + q * 8) * 2)) = *(uint4*)hh;
            }
            s += __shfl_xor_sync(0xffffffffu, s, 1);
            if ((t & 1) == 0) atomicAdd(&g_S1[j0 + wj], s);
        }
        if (ch == 0) A_LDD(ibase0 + 64);
        if (ch == 0) CP_WAIT(1); else CP_WAIT(0);
        __syncthreads();
        uint32_t xab = sb + 16384 + ch * 8192;
        #pragma unroll
        for (int ks = 0; ks < 4; ks++) {
            int k0 = ks * 16;
            uint32_t Awh[4];
            ldm_x4(Awh, frag_addr(sb, lane, w * 16, k0));
            #pragma unroll
            for (int gq = 0; gq < 4; gq++) {
                uint32_t Bh[4];
                ldm_x4t(Bh, frag_addr(xab, lane, k0, gq * 16));
                #pragma unroll
                for (int h = 0; h < 2; h++) {
                    uint32_t bh[2] = {Bh[h * 2], Bh[h * 2 + 1]};
                    mma16816(C[gq * 2 + h], Awh, bh);
                }
            }
        }
    }
    const int g = lane >> 2, tg = lane & 3;
    #pragma unroll
    for (int ni = 0; ni < 8; ni++)
        #pragma unroll
        for (int e = 0; e < 4; e++) {
            int j = j0 + w * 16 + g + (e >> 1) * 8;
            int p = ni * 8 + tg * 2 + (e & 1);
            atomicAdd(&g_mun[(size_t)j * P + p], C[ni][e]);
        }
}

// ---------------- K: U — 2 rows per warp (Uh only) ----------------
__global__ void k_U(const float* __restrict__ x, int n) {
    int w0 = (blockIdx.x * blockDim.x + threadIdx.x) >> 5;
    int lane = threadIdx.x & 31;
    if (w0 >= n / 2) return;
    #pragma unroll
    for (int rr = 0; rr < 2; rr++) {
        int w = w0 + rr * (n / 2);
        float S1 = g_S1[w];
        float mu0 = g_mun[(size_t)w * P + lane];
        float mu1 = g_mun[(size_t)w * P + 32 + lane];
        float x0 = x[(size_t)w * P + lane];
        float x1 = x[(size_t)w * P + 32 + lane];
        mu0 /= S1; mu1 /= S1;
        if (isnan(mu0)) mu0 = x0;
        if (isnan(mu1)) mu1 = x1;
        float U0 = x0 - mu0, U1 = x1 - mu1;
        g_Uh[(size_t)w * P + lane]      = __float2half_rn(U0);
        g_Uh[(size_t)w * P + 32 + lane] = __float2half_rn(U1);
        float b = x0 * U0 + x1 * U1;
        float un2 = U0 * U0 + U1 * U1;
        #pragma unroll
        for (int o = 16; o; o >>= 1) {
            b += __shfl_xor_sync(0xffffffffu, b, o);
            un2 += __shfl_xor_sync(0xffffffffu, un2, o);
        }
        if (lane == 0) { g_bU[w] = b; g_sU2[w] = sqrtf(un2); }
    }
}

// ---------------- K: beta — cp.async x-tiles + reg-prefetch D2; c-GEMM(x2) + acc(x1) ----------------
// dyn smem: Wh 0 (16K), DST 16384 (16K), XB0 32768 (xh 8K + xl 8K), XB1 49152 (16K),
//           bU 65536(512), su2 66048(512) -> 66560 ; grid (n/128, 16), 4 chunks
__global__ void __launch_bounds__(256, 2) k_beta(const float* __restrict__ pr1,
                                                 const float* __restrict__ pr2, int n) {
    extern __shared__ char smc[];
    uint32_t sb = su32(smc);
    float* bUs  = (float*)(smc + 65536);
    float* su2s = (float*)(smc + 66048);
    const int t = threadIdx.x, w = t >> 5, lane = t & 31;
    const int j0 = blockIdx.x * 128;
    const int ibase0 = blockIdx.y * 256;
    const float md = sqrtf(__uint_as_float(g_maxbits));
    const float rr1 = fminf(*pr1, md), rr2 = fminf(*pr2, md);
    const float a1 = 2.0f / rr1, a2 = 2.0f / rr2;
    const int g = lane >> 2, tg = lane & 3;
    const int xrow = t >> 3, xcb = (t & 7) * 16;
    const int drj = t >> 3, drc = t & 7;

    #define CPX(bbase, ib) do { \
        uint32_t _o0 = SWZ(xrow * 128 + xcb), _o1 = SWZ((32 + xrow) * 128 + xcb); \
        cp16((bbase) + _o0,        &g_xh[(size_t)((ib) + xrow) * P + xcb / 2]); \
        cp16((bbase) + _o1,        &g_xh[(size_t)((ib) + 32 + xrow) * P + xcb / 2]); \
        cp16((bbase) + 8192 + _o0, &g_xl[(size_t)((ib) + xrow) * P + xcb / 2]); \
        cp16((bbase) + 8192 + _o1, &g_xl[(size_t)((ib) + 32 + xrow) * P + xcb / 2]); \
    } while (0)
    uint4 pdq[4];
    #define B_LDD(ib) do { \
        pdq[0] = *(const uint4*)&g_D2h[(size_t)(j0 + drj) * n + (ib) + drc * 8]; \
        pdq[1] = *(const uint4*)&g_D2h[(size_t)(j0 + 32 + drj) * n + (ib) + drc * 8]; \
        pdq[2] = *(const uint4*)&g_D2h[(size_t)(j0 + 64 + drj) * n + (ib) + drc * 8]; \
        pdq[3] = *(const uint4*)&g_D2h[(size_t)(j0 + 96 + drj) * n + (ib) + drc * 8]; \
    } while (0)

    CPX(sb + 32768, ibase0);
    CP_COMMIT();
    CPX(sb + 49152, ibase0 + 64);
    CP_COMMIT();
    B_LDD(ibase0);

    // stage Uh only; cache A fragments
    for (int q = t; q < 1024; q += 256) {
        int row = q >> 3, cb = (q & 7) * 16;
        *(uint4*)(smc + SWZ(row * 128 + cb)) = *(const uint4*)&g_Uh[(size_t)(j0 + row) * P + cb / 2];
    }
    if (t < 128) { bUs[t] = g_bU[j0 + t]; su2s[t] = g_sU2[j0 + t]; }
    __syncthreads();
    uint32_t AUh[4][4];
    #pragma unroll
    for (int ks = 0; ks < 4; ks++)
        ldm_x4(AUh[ks], frag_addr(sb, lane, w * 16, ks * 16));

    float accC[8][4];
    #pragma unroll
    for (int b = 0; b < 8; b++)
        #pragma unroll
        for (int e = 0; e < 4; e++) accC[b][e] = 0.f;

    #pragma unroll 1
    for (int ch = 0; ch < 4; ch++) {
        int ib = ibase0 + ch * 64;
        if (ch) __syncthreads();
        #pragma unroll
        for (int m = 0; m < 4; m++) {
            int j = drj + 32 * m;
            *(uint4*)(smc + 16384 + j * 128 + ((drc * 16) ^ ((j & 7) << 4))) = pdq[m];
        }
        if (ch >= 1 && ch <= 2) { CPX(sb + 32768 + ((ch + 1) & 1) * 16384, ibase0 + (ch + 1) * 64); CP_COMMIT(); }
        if (ch < 3) B_LDD(ib + 64);
        if (ch < 3) CP_WAIT(1); else CP_WAIT(0);
        __syncthreads();
        uint32_t xbh = sb + 32768 + (ch & 1) * 16384;
        uint32_t xbl = xbh + 8192;

        float cC[8][4];
        #pragma unroll
        for (int b = 0; b < 8; b++)
            #pragma unroll
            for (int e = 0; e < 4; e++) cC[b][e] = 0.f;
        #pragma unroll
        for (int ks = 0; ks < 4; ks++) {
            int k0 = ks * 16;
            #pragma unroll
            for (int gq = 0; gq < 4; gq++) {
                uint32_t Bh[4], Bl[4];
                ldm_x4(Bh, frag_addr(xbh, lane, gq * 16, k0));
                ldm_x4(Bl, frag_addr(xbl, lane, gq * 16, k0));
                #pragma unroll
                for (int h = 0; h < 2; h++) {
                    int ni = gq * 2 + h;
                    uint32_t bh[2] = {Bh[h], Bh[h + 2]};
                    uint32_t bl[2] = {Bl[h], Bl[h + 2]};
                    mma16816(cC[ni], AUh[ks], bh);
                    mma16816(cC[ni], AUh[ks], bl);
                }
            }
        }
        #pragma unroll
        for (int e2 = 0; e2 < 2; e2++) {
            int jl = w * 16 + g + e2 * 8;
            float bj = bUs[jl], su2 = su2s[jl];
            float rs = 0.f;
            #pragma unroll
            for (int ni = 0; ni < 8; ni++) {
                int il = ni * 8 + tg * 2;
                float2 dd = __half22float2(
                    *(__half2*)(smc + 16384 + jl * 128 + ((il * 2) ^ ((jl & 7) << 4))));
                float wv[2], d2v[2] = {dd.x, dd.y};
                #pragma unroll
                for (int q = 0; q < 2; q++) {
                    float cp = cC[ni][e2 * 2 + q] - bj;
                    float du = fmaxf(fabsf(cp) * su2, 1e-3f);
                    float dv = asqrt(fmaxf(d2v[q] - du * du, 1e-6f));
                    wv[q] = w2f(dv, a1) * w2f(du, a2);
                }
                rs += wv[0] + wv[1];
                *(uint32_t*)(smc + SWZ(jl * 128 + il * 2)) = packh2(wv[0], wv[1]);
            }
            rs += __shfl_xor_sync(0xffffffffu, rs, 1);
            rs += __shfl_xor_sync(0xffffffffu, rs, 2);
            if (tg == 0) atomicAdd(&g_S2[j0 + jl], rs);
        }
        __syncthreads();
        #pragma unroll
        for (int ks = 0; ks < 4; ks++) {
            int k0 = ks * 16;
            uint32_t Awh[4];
            ldm_x4(Awh, frag_addr(sb, lane, w * 16, k0));
            #pragma unroll
            for (int gq = 0; gq < 4; gq++) {
                uint32_t Bh[4];
                ldm_x4t(Bh, frag_addr(xbh, lane, k0, gq * 16));
                #pragma unroll
                for (int h = 0; h < 2; h++) {
                    uint32_t bh[2] = {Bh[h * 2], Bh[h * 2 + 1]};
                    mma16816(accC[gq * 2 + h], Awh, bh);
                }
            }
        }
    }
    #pragma unroll
    for (int ni = 0; ni < 8; ni++)
        #pragma unroll
        for (int e = 0; e < 4; e++) {
            int j = j0 + w * 16 + g + (e >> 1) * 8;
            int p = ni * 8 + tg * 2 + (e & 1);
            atomicAdd(&g_accZ[(size_t)j * P + p], accC[ni][e]);
        }
}

// ---------------- K: output (float2 vectorized) ----------------
__global__ void k_out(const float* __restrict__ x, float* __restrict__ out, int n) {
    int idx = blockIdx.x * blockDim.x + threadIdx.x;
    if (idx >= n * P / 2) return;
    int j = idx >> 5;
    float S2 = g_S2[j];
    float2 acc = *(const float2*)&g_accZ[(size_t)idx * 2];
    float2 xv = *(const float2*)&x[(size_t)idx * 2];
    float e0 = acc.x / S2, e1 = acc.y / S2;
    if (isnan(e0)) e0 = xv.x;
    if (isnan(e1)) e1 = xv.y;
    *(float2*)&out[(size_t)idx * 2] = make_float2(e0, e1);
}

extern "C" void kernel_launch(void* const* d_in, const int* in_sizes, int n_in,
                              void* d_out, int out_size) {
    const float* x  = (const float*)d_in[0];
    const float* r0 = (const float*)d_in[1];
    const float* r1 = (const float*)d_in[2];
    const float* r2 = (const float*)d_in[3];
    float* out = (float*)d_out;
    const int n = in_sizes[0] / P;  // 4096
    const int nb = n / 128;

    k_prep<<<(n + 7) / 8, 256>>>(x, n);

    cudaFuncSetAttribute(k_gram, cudaFuncAttributeMaxDynamicSharedMemorySize, 50176);
    k_gram<<<nb * (nb + 1) / 2, 256, 50176>>>(n);

    cudaFuncSetAttribute(k_alpha, cudaFuncAttributeMaxDynamicSharedMemorySize, 32768);
    k_alpha<<<dim3(nb, 32), 256, 32768>>>(r0, n);

    k_U<<<(n / 2 + 7) / 8, 256>>>(x, n);

    cudaFuncSetAttribute(k_beta, cudaFuncAttributeMaxDynamicSharedMemorySize, 66560);
    k_beta<<<dim3(nb, 16), 256, 66560>>>(r1, r2, n);

    k_out<<<(n * P / 2 + 255) / 256, 256>>>(x, out, n);
}